// round 12
// baseline (speedup 1.0000x reference)
#include <cuda_runtime.h>
#include <cuda_fp16.h>
#include <math.h>
#include <stdint.h>

// ---------------- constants ----------------
#define NROW 4096
#define DIM  512
#define SLEN_ 1024
#define DH 64
#define NMELEM (NROW*DIM)
#define NEDGE_ 34

#define BM 128
#define BKK 16
#define ASTRH 24
#define BSTRH_NK 24

struct Route {
    int   act;
    float aw;
    int   op[3];
    int   src[3];
    int   edge[3];
    float w[3];
    int   has[3];
};

// ---------------- device globals ----------------
__device__ __align__(16) float g_outs[10][NMELEM];
__device__ __align__(16) float g_eln[3][NMELEM];
__device__ __align__(16) float g_qkv[3][NMELEM];
__device__ __align__(16) float g_ln[NMELEM];
__device__ __align__(16) float g_t[4][NMELEM];
__device__ __align__(16) float g_scores[(size_t)32*SLEN_*SLEN_];
__device__ const float* g_srcp[10];
__device__ Route g_routes[8];
__device__ int   g_rem[8];

// ---------------- helpers ----------------
__device__ __forceinline__ float geluf(float x){
    float x3 = x*x*x;
    return 0.5f*x*(1.0f + tanhf(0.7978845608028654f*(x + 0.044715f*x3)));
}
__device__ __forceinline__ float sigm(float x){ return 1.0f/(1.0f+expf(-x)); }

// block (128 thr) row LN reduction (used by node_final / k_final)
__device__ __forceinline__ void row_stats(float4 v, float* red, float& mean, float& rstd){
    int t = threadIdx.x;
    float s = v.x+v.y+v.z+v.w;
    red[t]=s; __syncthreads();
    #pragma unroll
    for (int st=64; st>0; st>>=1){ if (t<st) red[t]+=red[t+st]; __syncthreads(); }
    mean = red[0]*(1.0f/DIM);
    __syncthreads();
    float dx=v.x-mean, dy=v.y-mean, dz=v.z-mean, dw=v.w-mean;
    red[t]=dx*dx+dy*dy+dz*dz+dw*dw; __syncthreads();
    #pragma unroll
    for (int st=64; st>0; st>>=1){ if (t<st) red[t]+=red[t+st]; __syncthreads(); }
    rstd = rsqrtf(red[0]*(1.0f/DIM) + 1e-6f);
    __syncthreads();
}

__device__ __forceinline__ void sp16(float x0, float x1, uint32_t& h, uint32_t& l){
    __half2 hh = __floats2half2_rn(x0, x1);
    float2 hf = __half22float2(hh);
    __half2 ll = __floats2half2_rn(x0 - hf.x, x1 - hf.y);
    h = *(uint32_t*)&hh; l = *(uint32_t*)&ll;
}
__device__ __forceinline__ uint32_t smem_u32(const void* p){
    return (uint32_t)__cvta_generic_to_shared(p);
}
__device__ __forceinline__ void mma_f16r(float* c, const uint32_t* a, const uint32_t* b){
    asm volatile("mma.sync.aligned.m16n8k16.row.col.f32.f16.f16.f32 "
        "{%0,%1,%2,%3},{%4,%5,%6,%7},{%8,%9},{%0,%1,%2,%3};"
        : "+f"(c[0]),"+f"(c[1]),"+f"(c[2]),"+f"(c[3])
        : "r"(a[0]),"r"(a[1]),"r"(a[2]),"r"(a[3]),"r"(b[0]),"r"(b[1]));
}
__device__ __forceinline__ void ldm_x4(uint32_t& r0,uint32_t& r1,uint32_t& r2,uint32_t& r3, const uint16_t* p){
    uint32_t a = smem_u32(p);
    asm volatile("ldmatrix.sync.aligned.m8n8.x4.shared.b16 {%0,%1,%2,%3},[%4];"
        : "=r"(r0),"=r"(r1),"=r"(r2),"=r"(r3) : "r"(a));
}
__device__ __forceinline__ void ldm_x4t(uint32_t& r0,uint32_t& r1,uint32_t& r2,uint32_t& r3, const uint16_t* p){
    uint32_t a = smem_u32(p);
    asm volatile("ldmatrix.sync.aligned.m8n8.x4.trans.shared.b16 {%0,%1,%2,%3},[%4];"
        : "=r"(r0),"=r"(r1),"=r"(r2),"=r"(r3) : "r"(a));
}

// ---------------- R3 GEMM core: 128x64, BK=16, fp16 hi/lo 3-term ----------------
template<bool TRANSB>
__device__ __forceinline__ void gemm_tc(const float* __restrict__ A, int lda,
                                        const float* __restrict__ B, int ldb,
                                        int K, int row0, int col0,
                                        float (*acc)[4])
{
    constexpr int BSTR = 64 + 8;
    constexpr int BS = TRANSB ? (64*BSTRH_NK) : (BKK*BSTR);

    __shared__ __align__(16) uint16_t As_hi[2][BM*ASTRH];
    __shared__ __align__(16) uint16_t As_lo[2][BM*ASTRH];
    __shared__ __align__(16) uint16_t Bs_hi[2][BS];
    __shared__ __align__(16) uint16_t Bs_lo[2][BS];

    int tid = threadIdx.x;
    int wid = tid >> 5, lane = tid & 31;
    int wm = wid >> 1, wn = wid & 1;

    int rA = tid >> 1, koA = (tid & 1)*8;
    int nB = tid >> 2, koB = (tid & 3)*4;
    int kB = tid >> 4, nqB = (tid & 15)*4;

    float4 a0r, a1r, b0r;
    auto ldg = [&](int it){
        int k0 = it*BKK;
        const float* ap = A + (size_t)(row0+rA)*lda + k0 + koA;
        a0r = *(const float4*)ap;
        a1r = *(const float4*)(ap+4);
        if (TRANSB) b0r = *(const float4*)(B + (size_t)(col0+nB)*ldb + k0 + koB);
        else        b0r = *(const float4*)(B + (size_t)(k0+kB)*ldb + col0 + nqB);
    };
    auto cvtstore = [&](int buf){
        uint32_t h0,h1,h2,h3,l0,l1,l2,l3;
        sp16(a0r.x,a0r.y,h0,l0); sp16(a0r.z,a0r.w,h1,l1);
        sp16(a1r.x,a1r.y,h2,l2); sp16(a1r.z,a1r.w,h3,l3);
        *(uint4*)&As_hi[buf][rA*ASTRH + koA] = make_uint4(h0,h1,h2,h3);
        *(uint4*)&As_lo[buf][rA*ASTRH + koA] = make_uint4(l0,l1,l2,l3);
        uint32_t bh0,bh1,bl0,bl1;
        sp16(b0r.x,b0r.y,bh0,bl0); sp16(b0r.z,b0r.w,bh1,bl1);
        if (TRANSB){
            *(uint2*)&Bs_hi[buf][nB*BSTRH_NK + koB] = make_uint2(bh0,bh1);
            *(uint2*)&Bs_lo[buf][nB*BSTRH_NK + koB] = make_uint2(bl0,bl1);
        } else {
            *(uint2*)&Bs_hi[buf][kB*BSTR + nqB] = make_uint2(bh0,bh1);
            *(uint2*)&Bs_lo[buf][kB*BSTR + nqB] = make_uint2(bl0,bl1);
        }
    };

    int nit = K / BKK;
    ldg(0); cvtstore(0);
    __syncthreads();
    int buf = 0;
    int aro = ((lane>>3)&1)*8 + (lane&7);
    int aco = (lane>>4)*8;
    #pragma unroll 1
    for (int it=0; it<nit; it++){
        bool more = (it+1 < nit);
        if (more) ldg(it+1);

        uint32_t ah[2][4], al[2][4];
        #pragma unroll
        for (int mt=0; mt<2; mt++){
            int mbase = wm*32 + mt*16;
            ldm_x4(ah[mt][0],ah[mt][1],ah[mt][2],ah[mt][3], &As_hi[buf][(mbase+aro)*ASTRH + aco]);
            ldm_x4(al[mt][0],al[mt][1],al[mt][2],al[mt][3], &As_lo[buf][(mbase+aro)*ASTRH + aco]);
        }
        uint32_t bh[4][2], bl[4][2];
        #pragma unroll
        for (int np=0; np<2; np++){
            int nbase = wn*32 + np*16;
            uint32_t r0,r1,r2,r3;
            if (TRANSB){
                int nrow = nbase + (lane>>4)*8 + (lane&7);
                int kcol = ((lane>>3)&1)*8;
                ldm_x4(r0,r1,r2,r3, &Bs_hi[buf][nrow*BSTRH_NK + kcol]);
                bh[np*2][0]=r0; bh[np*2][1]=r1; bh[np*2+1][0]=r2; bh[np*2+1][1]=r3;
                ldm_x4(r0,r1,r2,r3, &Bs_lo[buf][nrow*BSTRH_NK + kcol]);
                bl[np*2][0]=r0; bl[np*2][1]=r1; bl[np*2+1][0]=r2; bl[np*2+1][1]=r3;
            } else {
                int krow = ((lane>>3)&1)*8 + (lane&7);
                int ncol = nbase + (lane>>4)*8;
                ldm_x4t(r0,r1,r2,r3, &Bs_hi[buf][krow*BSTR + ncol]);
                bh[np*2][0]=r0; bh[np*2][1]=r1; bh[np*2+1][0]=r2; bh[np*2+1][1]=r3;
                ldm_x4t(r0,r1,r2,r3, &Bs_lo[buf][krow*BSTR + ncol]);
                bl[np*2][0]=r0; bl[np*2][1]=r1; bl[np*2+1][0]=r2; bl[np*2+1][1]=r3;
            }
        }
        #pragma unroll
        for (int mt=0; mt<2; mt++)
            #pragma unroll
            for (int nt=0; nt<4; nt++){
                mma_f16r(acc[mt*4+nt], ah[mt], bh[nt]);
                mma_f16r(acc[mt*4+nt], al[mt], bh[nt]);
                mma_f16r(acc[mt*4+nt], ah[mt], bl[nt]);
            }

        if (more) cvtstore(buf^1);
        __syncthreads();
        buf ^= 1;
    }
}

#define EPI_BEGIN { \
    int lane = threadIdx.x & 31, wid_ = threadIdx.x >> 5; \
    int wm = wid_ >> 1, wn = wid_ & 1, g = lane >> 2, t = lane & 3; \
    _Pragma("unroll") \
    for (int mt=0; mt<2; mt++) \
    _Pragma("unroll") \
    for (int nt=0; nt<4; nt++) \
    _Pragma("unroll") \
    for (int h2=0; h2<2; h2++){ \
        int rr = row0 + wm*32 + mt*16 + g + h2*8; \
        int cc = col0 + wn*32 + nt*8 + 2*t; \
        float v0 = acc[mt*4+nt][h2*2]; \
        float v1 = acc[mt*4+nt][h2*2+1];
#define EPI_END }}

// ---------------- routing (+ source pointer table) ----------------
__global__ void k_route(const float* __restrict__ node_p, const float* __restrict__ edge_p,
                        const float* inpute, const float* inputo){
    if (threadIdx.x != 0 || blockIdx.x != 0) return;
    g_srcp[0] = inpute;
    g_srcp[1] = inputo;
    for (int i = 0; i < 8; i++) g_srcp[2+i] = g_outs[2+i];
    bool processed[8];
    for (int i=0;i<8;i++) processed[i]=false;
    int lind = 0;
    for (int c=0;c<8;c++){
        int nsrc = (c+2 < 5) ? (c+2) : 5;
        int snode = c - nsrc;
        int L = nsrc*5;
        const float* npc = node_p + c*8;
        int act = 0; float bm = npc[0];
        for (int i=1;i<8;i++) if (npc[i] > bm){ bm=npc[i]; act=i; }
        float ssum = 0.0f;
        for (int i=0;i<8;i++) ssum += expf(npc[i]-bm);
        float aw = expf(npc[act]-bm)/ssum;

        Route r; r.act=act; r.aw=aw;
        for (int z=0;z<3;z++){ r.has[z]=0; r.op[z]=0; r.src[z]=0; r.edge[z]=0; r.w[z]=0.0f; }

        #define EPV(i,j) edge_p[((i)*NEDGE_ + lind + (j)/5)*5 + ((j)%5)]

        int qs = 5; float qbm = EPV(0,5);
        for (int j=6;j<L;j++){ float v=EPV(0,j); if (v>qbm){qbm=v;qs=j;} }
        float qsum = 0.0f;
        for (int j=5;j<L;j++) qsum += expf(EPV(0,j)-qbm);
        {
            int se = qs/5;
            r.op[0]=qs%5; r.src[0]=(se==0)?0:(snode+se+2); r.edge[0]=lind+se; r.w[0]=1.0f/qsum; r.has[0]=1;
            if (r.src[0]>=2) processed[r.src[0]-2]=true;
        }
        if (act < 7){
            int lo = (act>0) ? 5 : 0;
            int ks = lo; float kbm = EPV(1,lo);
            for (int j=lo+1;j<L;j++){ float v=EPV(1,j); if (v>kbm){kbm=v;ks=j;} }
            float ksum = 0.0f;
            for (int j=lo;j<L;j++) ksum += expf(EPV(1,j)-kbm);
            {
                int se = ks/5;
                r.op[1]=ks%5; r.src[1]=(se==0)?0:(snode+se+2); r.edge[1]=lind+se; r.w[1]=1.0f/ksum; r.has[1]=1;
                if (r.src[1]>=2) processed[r.src[1]-2]=true;
            }
            if (act < 5){
                int vs; float vw;
                if (act==0 && ks<5){
                    vs = 0; float vbm = EPV(2,0);
                    for (int j=1;j<5;j++){ float v=EPV(2,j); if (v>vbm){vbm=v;vs=j;} }
                    float vsum=0.0f;
                    for (int j=0;j<5;j++) vsum += expf(EPV(2,j)-vbm);
                    vw = 1.0f/vsum;
                } else {
                    vs = lo; float vbm = EPV(2,lo);
                    for (int j=lo+1;j<L;j++){ float v=EPV(2,j); if (v>vbm){vbm=v;vs=j;} }
                    float vsum=0.0f;
                    for (int j=lo;j<L;j++) vsum += expf(EPV(2,j)-vbm);
                    vw = 1.0f/vsum;
                }
                int se = vs/5;
                r.op[2]=vs%5; r.src[2]=(se==0)?0:(snode+se+2); r.edge[2]=lind+se; r.w[2]=vw; r.has[2]=1;
                if (r.src[2]>=2) processed[r.src[2]-2]=true;
            }
        }
        #undef EPV
        g_routes[c] = r;
        lind += nsrc;
    }
    for (int i=0;i<8;i++) g_rem[i] = processed[i]?0:1;
}

// ---------------- edge prep: warp-per-row LN / identity (8 rows per block) ----------------
__global__ void k_edge_prep(int c, const float* __restrict__ eg, const float* __restrict__ ebeta){
    int z = blockIdx.z;
    if (!g_routes[c].has[z]) return;
    int op = g_routes[c].op[z];
    if (op == 3) return;
    int w = threadIdx.x >> 5, lane = threadIdx.x & 31;
    int row = blockIdx.x*8 + w;
    const float4* x = (const float4*)(g_srcp[g_routes[c].src[z]] + (size_t)row*DIM);
    float4 v[4];
    #pragma unroll
    for (int j=0;j<4;j++) v[j] = x[lane + 32*j];
    if (op == 4){
        float ww = g_routes[c].w[z];
        float4* o = (float4*)(g_qkv[z] + (size_t)row*DIM);
        #pragma unroll
        for (int j=0;j<4;j++) o[lane + 32*j] = make_float4(ww*v[j].x, ww*v[j].y, ww*v[j].z, ww*v[j].w);
        return;
    }
    float s = 0.f, q = 0.f;
    #pragma unroll
    for (int j=0;j<4;j++){
        s += v[j].x+v[j].y+v[j].z+v[j].w;
        q += v[j].x*v[j].x+v[j].y*v[j].y+v[j].z*v[j].z+v[j].w*v[j].w;
    }
    #pragma unroll
    for (int o2=16;o2>0;o2>>=1){
        s += __shfl_xor_sync(0xFFFFFFFFu, s, o2);
        q += __shfl_xor_sync(0xFFFFFFFFu, q, o2);
    }
    float mean = s*(1.0f/DIM);
    float rstd = rsqrtf(q*(1.0f/DIM) - mean*mean + 1e-6f);
    int e = g_routes[c].edge[z];
    const float4* gg = (const float4*)(eg    + (size_t)e*DIM);
    const float4* bb = (const float4*)(ebeta + (size_t)e*DIM);
    float4* o = (float4*)(g_eln[z] + (size_t)row*DIM);
    #pragma unroll
    for (int j=0;j<4;j++){
        float4 g4 = gg[lane + 32*j], b4 = bb[lane + 32*j];
        float4 r;
        r.x=(v[j].x-mean)*rstd*g4.x+b4.x; r.y=(v[j].y-mean)*rstd*g4.y+b4.y;
        r.z=(v[j].z-mean)*rstd*g4.z+b4.z; r.w=(v[j].w-mean)*rstd*g4.w+b4.w;
        o[lane + 32*j] = r;
    }
}

// ---------------- edge GEMM ----------------
__global__ void __launch_bounds__(256, 3) k_edge_gemm(int c, const float* __restrict__ eW, const float* __restrict__ eb){
    int z = blockIdx.z;
    if (!g_routes[c].has[z]) return;
    int op = g_routes[c].op[z];
    if (op == 4) return;
    int e = g_routes[c].edge[z];
    const float* A = (op <= 2) ? g_eln[z] : g_srcp[g_routes[c].src[z]];
    const float* W = eW + (size_t)e*DIM*DIM;
    int row0 = blockIdx.y*BM, col0 = blockIdx.x*64;
    float acc[8][4] = {};
    gemm_tc<false>(A, DIM, W, DIM, DIM, row0, col0, acc);
    float w = g_routes[c].w[z];
    const float* bias = eb + (size_t)e*DIM;
    EPI_BEGIN
        v0 += bias[cc]; v1 += bias[cc+1];
        if (op==0){ v0=fmaxf(v0,0.f); v1=fmaxf(v1,0.f); }
        else if (op==1){ v0=geluf(v0); v1=geluf(v1); }
        *(float2*)&g_qkv[z][(size_t)rr*DIM + cc] = make_float2(w*v0, w*v1);
    EPI_END
}

// ---------------- node LN (act 0; warp-per-row, 8 rows per block) ----------------
__global__ void k_node_ln(int c, const float* __restrict__ ng, const float* __restrict__ nbeta){
    if (g_routes[c].act != 0) return;
    int w = threadIdx.x >> 5, lane = threadIdx.x & 31;
    int row = blockIdx.x*8 + w;
    const float4* x = (const float4*)(g_qkv[0] + (size_t)row*DIM);
    float4 v[4];
    #pragma unroll
    for (int j=0;j<4;j++) v[j] = x[lane + 32*j];
    float s = 0.f, q = 0.f;
    #pragma unroll
    for (int j=0;j<4;j++){
        s += v[j].x+v[j].y+v[j].z+v[j].w;
        q += v[j].x*v[j].x+v[j].y*v[j].y+v[j].z*v[j].z+v[j].w*v[j].w;
    }
    #pragma unroll
    for (int o2=16;o2>0;o2>>=1){
        s += __shfl_xor_sync(0xFFFFFFFFu, s, o2);
        q += __shfl_xor_sync(0xFFFFFFFFu, q, o2);
    }
    float mean = s*(1.0f/DIM);
    float rstd = rsqrtf(q*(1.0f/DIM) - mean*mean + 1e-6f);
    const float4* gg = (const float4*)(ng    + (size_t)c*DIM);
    const float4* bb = (const float4*)(nbeta + (size_t)c*DIM);
    float4* o = (float4*)(g_ln + (size_t)row*DIM);
    #pragma unroll
    for (int j=0;j<4;j++){
        float4 g4 = gg[lane + 32*j], b4 = bb[lane + 32*j];
        float4 r;
        r.x=(v[j].x-mean)*rstd*g4.x+b4.x; r.y=(v[j].y-mean)*rstd*g4.y+b4.y;
        r.z=(v[j].z-mean)*rstd*g4.z+b4.z; r.w=(v[j].w-mean)*rstd*g4.w+b4.w;
        o[lane + 32*j] = r;
    }
}

// ---------------- node GEMMs W0/W1/W2 ----------------
__global__ void __launch_bounds__(256, 3) k_node_gemm123(int c, const float* __restrict__ nW, const float* __restrict__ nb){
    int act = g_routes[c].act;
    int z = blockIdx.z;
    const float* A; bool need, bias; int actf = 0;
    if (z == 0){
        need = (act==0||act==1||act==3);
        A = (act==0) ? g_ln : g_qkv[0];
        bias = (act!=3); actf = (act==1)?1:0;
    } else if (z == 1){
        need = (act==0||act==1||act==3||act==5);
        A = g_qkv[1];
        bias = (act!=3); actf = (act==5)?1:0;
    } else {
        need = (act==0||act==3);
        A = g_qkv[2];
        bias = (act==0);
    }
    if (!need) return;
    const float* W = nW + ((size_t)c*4 + z)*DIM*DIM;
    int row0 = blockIdx.y*BM, col0 = blockIdx.x*64;
    float acc[8][4] = {};
    gemm_tc<false>(A, DIM, W, DIM, DIM, row0, col0, acc);
    const float* bp = nb + ((size_t)c*4 + z)*DIM;
    EPI_BEGIN
        if (bias){ v0 += bp[cc]; v1 += bp[cc+1]; }
        if (actf){ v0 = geluf(v0); v1 = geluf(v1); }
        *(float2*)&g_t[z][(size_t)rr*DIM + cc] = make_float2(v0, v1);
    EPI_END
}

// ---------------- elementwise mid (512 blocks) ----------------
__global__ void k_node_mid(int c){
    int act = g_routes[c].act;
    if (act != 1 && act != 3) return;
    #pragma unroll
    for (int j=0;j<4;j++){
        size_t i = (size_t)blockIdx.x*1024 + j*256 + threadIdx.x;
        float4 a = ((const float4*)g_t[0])[i];
        float4 b = ((const float4*)g_t[1])[i];
        float4 o;
        if (act == 1){
            o = make_float4(a.x*b.x, a.y*b.y, a.z*b.z, a.w*b.w);
        } else {
            float4 d = ((const float4*)g_t[2])[i];
            o = make_float4(fmaxf(a.x+b.x+d.x,0.f), fmaxf(a.y+b.y+d.y,0.f),
                            fmaxf(a.z+b.z+d.z,0.f), fmaxf(a.w+b.w+d.w,0.f));
        }
        ((float4*)g_t[3])[i] = o;
    }
}

// ---------------- attention ----------------
__global__ void __launch_bounds__(256, 3) k_attn_scores(int c){
    if (g_routes[c].act != 0) return;
    int bz = blockIdx.z, b = bz >> 3, h = bz & 7;
    const float* A  = g_t[0] + (size_t)b*SLEN_*DIM + h*DH;
    const float* Bp = g_t[1] + (size_t)b*SLEN_*DIM + h*DH;
    int row0 = blockIdx.y*BM, col0 = blockIdx.x*64;
    float acc[8][4] = {};
    gemm_tc<true>(A, DIM, Bp, DIM, DH, row0, col0, acc);
    float* S = g_scores + (size_t)bz*SLEN_*SLEN_;
    EPI_BEGIN
        *(float2*)&S[(size_t)rr*SLEN_ + cc] = make_float2(v0*0.125f, v1*0.125f);
    EPI_END
}

// softmax: 32 rows per block, warp-per-row (grid 32 x 32)
__global__ void k_attn_softmax(int c){
    if (g_routes[c].act != 0) return;
    int bz = blockIdx.y;
    int w = threadIdx.x >> 5, lane = threadIdx.x & 31;
    #pragma unroll 1
    for (int rr = w; rr < 32; rr += 8){
        int row = blockIdx.x*32 + rr;
        float4* p = (float4*)(g_scores + ((size_t)bz*SLEN_ + row)*SLEN_);
        float4 v[8];
        float m = -1e30f;
        #pragma unroll
        for (int j=0;j<8;j++){
            v[j] = p[lane + 32*j];
            m = fmaxf(m, fmaxf(fmaxf(v[j].x,v[j].y), fmaxf(v[j].z,v[j].w)));
        }
        #pragma unroll
        for (int o=16;o>0;o>>=1) m = fmaxf(m, __shfl_xor_sync(0xFFFFFFFFu, m, o));
        float s = 0.f;
        #pragma unroll
        for (int j=0;j<8;j++){
            v[j].x=expf(v[j].x-m); v[j].y=expf(v[j].y-m);
            v[j].z=expf(v[j].z-m); v[j].w=expf(v[j].w-m);
            s += v[j].x+v[j].y+v[j].z+v[j].w;
        }
        #pragma unroll
        for (int o=16;o>0;o>>=1) s += __shfl_xor_sync(0xFFFFFFFFu, s, o);
        float inv = 1.0f/s;
        #pragma unroll
        for (int j=0;j<8;j++){
            v[j].x*=inv; v[j].y*=inv; v[j].z*=inv; v[j].w*=inv;
            p[lane + 32*j] = v[j];
        }
    }
}

__global__ void __launch_bounds__(256, 3) k_attn_av(int c){
    if (g_routes[c].act != 0) return;
    int bz = blockIdx.z, b = bz >> 3, h = bz & 7;
    const float* A  = g_scores + (size_t)bz*SLEN_*SLEN_;
    const float* Bp = g_t[2] + (size_t)b*SLEN_*DIM + h*DH;
    int row0 = blockIdx.y*BM, col0 = 0;
    float acc[8][4] = {};
    gemm_tc<false>(A, SLEN_, Bp, DIM, SLEN_, row0, col0, acc);
    EPI_BEGIN
        *(float2*)&g_t[3][(size_t)(b*SLEN_ + rr)*DIM + h*DH + cc] = make_float2(v0, v1);
    EPI_END
}

// ---------------- node GEMM W3 ----------------
__global__ void __launch_bounds__(256, 3) k_node_gemm4(int c, const float* __restrict__ nW, const float* __restrict__ nb){
    int act = g_routes[c].act;
    if (!(act==0||act==1||act==3)) return;
    const float* W = nW + ((size_t)c*4 + 3)*DIM*DIM;
    int row0 = blockIdx.y*BM, col0 = blockIdx.x*64;
    float acc[8][4] = {};
    gemm_tc<false>(g_t[3], DIM, W, DIM, DIM, row0, col0, acc);
    const float* bp = nb + ((size_t)c*4 + 3)*DIM;
    EPI_BEGIN
        *(float2*)&g_t[1][(size_t)rr*DIM + cc] = make_float2(v0 + bp[cc], v1 + bp[cc+1]);
    EPI_END
}

// ---------------- node finalize ----------------
__global__ void k_node_final(int c, const float* __restrict__ ng, const float* __restrict__ nbeta){
    int act = g_routes[c].act;
    float aw = g_routes[c].aw;
    int row = blockIdx.x, t = threadIdx.x;
    size_t off = (size_t)row*DIM;
    float4 q = ((const float4*)(g_qkv[0] + off))[t];
    float4 o;
    bool needln = false;
    float4 x = q;
    if (act==0 || act==1 || act==3 || act==5){
        float4 t1 = ((const float4*)(g_t[1] + off))[t];
        o = make_float4(q.x+t1.x, q.y+t1.y, q.z+t1.z, q.w+t1.w);
    } else if (act==2){
        float4 k = ((const float4*)(g_qkv[1] + off))[t];
        float4 v = ((const float4*)(g_qkv[2] + off))[t];
        x = make_float4(q.x+k.x+v.x, q.y+k.y+v.y, q.z+k.z+v.z, q.w+k.w+v.w);
        needln = true;
    } else if (act==4){
        float4 k = ((const float4*)(g_qkv[1] + off))[t];
        float4 v = ((const float4*)(g_qkv[2] + off))[t];
        o = make_float4(q.x*sigm(k.x)+v.x, q.y*sigm(k.y)+v.y, q.z*sigm(k.z)+v.z, q.w*sigm(k.w)+v.w);
    } else if (act==6){
        float4 k = ((const float4*)(g_qkv[1] + off))[t];
        o = make_float4(q.x+k.x, q.y+k.y, q.z+k.z, q.w+k.w);
    } else {
        needln = true;
    }
    __shared__ float red[128];
    if (needln){
        float mean, rstd;
        row_stats(x, red, mean, rstd);
        float4 g4 = ((const float4*)(ng    + (size_t)c*DIM))[t];
        float4 b4 = ((const float4*)(nbeta + (size_t)c*DIM))[t];
        o.x=(x.x-mean)*rstd*g4.x+b4.x; o.y=(x.y-mean)*rstd*g4.y+b4.y;
        o.z=(x.z-mean)*rstd*g4.z+b4.z; o.w=(x.w-mean)*rstd*g4.w+b4.w;
    }
    o.x*=aw; o.y*=aw; o.z*=aw; o.w*=aw;
    ((float4*)(g_outs[2+c] + off))[t] = o;
}

// ---------------- final sum + LN ----------------
__global__ void k_final(const float* __restrict__ og, const float* __restrict__ ob, float* __restrict__ out){
    int row = blockIdx.x, t = threadIdx.x;
    size_t off = (size_t)row*DIM;
    float4 s = make_float4(0.f,0.f,0.f,0.f);
    #pragma unroll
    for (int n=0;n<8;n++){
        if (g_rem[n]){
            float4 v = ((const float4*)(g_outs[2+n] + off))[t];
            s.x+=v.x; s.y+=v.y; s.z+=v.z; s.w+=v.w;
        }
    }
    __shared__ float red[128];
    float mean, rstd;
    row_stats(s, red, mean, rstd);
    float4 g4 = ((const float4*)og)[t];
    float4 b4 = ((const float4*)ob)[t];
    float4 o;
    o.x=(s.x-mean)*rstd*g4.x+b4.x; o.y=(s.y-mean)*rstd*g4.y+b4.y;
    o.z=(s.z-mean)*rstd*g4.z+b4.z; o.w=(s.w-mean)*rstd*g4.w+b4.w;
    ((float4*)(out + off))[t] = o;
}

// ---------------- launch ----------------
extern "C" void kernel_launch(void* const* d_in, const int* in_sizes, int n_in,
                              void* d_out, int out_size)
{
    const float* inpute    = (const float*)d_in[0];
    const float* inputo    = (const float*)d_in[1];
    const float* node_p    = (const float*)d_in[2];
    const float* edge_p    = (const float*)d_in[3];
    const float* edge_W    = (const float*)d_in[4];
    const float* edge_b    = (const float*)d_in[5];
    const float* edge_g    = (const float*)d_in[6];
    const float* edge_beta = (const float*)d_in[7];
    const float* node_W    = (const float*)d_in[8];
    const float* node_b    = (const float*)d_in[9];
    const float* node_g    = (const float*)d_in[10];
    const float* node_beta = (const float*)d_in[11];
    const float* out_g     = (const float*)d_in[12];
    const float* out_beta  = (const float*)d_in[13];
    float* out = (float*)d_out;

    k_route<<<1, 32>>>(node_p, edge_p, inpute, inputo);

    for (int c = 0; c < 8; c++){
        k_edge_prep<<<dim3(NROW/8,1,3), 256>>>(c, edge_g, edge_beta);
        k_edge_gemm<<<dim3(DIM/64, NROW/BM, 3), 256>>>(c, edge_W, edge_b);
        k_node_ln<<<NROW/8, 256>>>(c, node_g, node_beta);
        k_node_gemm123<<<dim3(DIM/64, NROW/BM, 3), 256>>>(c, node_W, node_b);
        k_node_mid<<<NMELEM/4/1024, 256>>>(c);
        k_attn_scores<<<dim3(SLEN_/64, SLEN_/BM, 32), 256>>>(c);
        k_attn_softmax<<<dim3(SLEN_/32, 32), 256>>>(c);
        k_attn_av<<<dim3(1, SLEN_/BM, 32), 256>>>(c);
        k_node_gemm4<<<dim3(DIM/64, NROW/BM), 256>>>(c, node_W, node_b);
        k_node_final<<<NROW, 128>>>(c, node_g, node_beta);
    }
    k_final<<<NROW, 128>>>(out_g, out_beta, out);
}

// round 13
// speedup vs baseline: 1.0412x; 1.0412x over previous
#include <cuda_runtime.h>
#include <cuda_fp16.h>
#include <math.h>
#include <stdint.h>

// ---------------- constants ----------------
#define NROW 4096
#define DIM  512
#define SLEN_ 1024
#define DH 64
#define NMELEM (NROW*DIM)
#define NEDGE_ 34

#define BM 128
#define BKK 16
#define ASTRH 24
#define BSTRH_NK 24

struct Route {
    int   act;
    float aw;
    int   op[3];
    int   src[3];
    int   edge[3];
    float w[3];
    int   has[3];
};

// ---------------- device globals ----------------
__device__ __align__(16) float g_outs[10][NMELEM];
__device__ __align__(16) float g_eln[3][NMELEM];
__device__ __align__(16) float g_qkv[3][NMELEM];
__device__ __align__(16) float g_ln[NMELEM];
__device__ __align__(16) float g_t[4][NMELEM];
__device__ __align__(16) float g_scores[(size_t)32*SLEN_*SLEN_];
__device__ const float* g_srcp[10];
__device__ Route g_routes[8];
__device__ int   g_rem[8];

// ---------------- helpers ----------------
__device__ __forceinline__ float geluf(float x){
    float x3 = x*x*x;
    return 0.5f*x*(1.0f + tanhf(0.7978845608028654f*(x + 0.044715f*x3)));
}
__device__ __forceinline__ float sigm(float x){ return 1.0f/(1.0f+expf(-x)); }

__device__ __forceinline__ void sp16(float x0, float x1, uint32_t& h, uint32_t& l){
    __half2 hh = __floats2half2_rn(x0, x1);
    float2 hf = __half22float2(hh);
    __half2 ll = __floats2half2_rn(x0 - hf.x, x1 - hf.y);
    h = *(uint32_t*)&hh; l = *(uint32_t*)&ll;
}
__device__ __forceinline__ uint32_t smem_u32(const void* p){
    return (uint32_t)__cvta_generic_to_shared(p);
}
__device__ __forceinline__ void mma_f16r(float* c, const uint32_t* a, const uint32_t* b){
    asm volatile("mma.sync.aligned.m16n8k16.row.col.f32.f16.f16.f32 "
        "{%0,%1,%2,%3},{%4,%5,%6,%7},{%8,%9},{%0,%1,%2,%3};"
        : "+f"(c[0]),"+f"(c[1]),"+f"(c[2]),"+f"(c[3])
        : "r"(a[0]),"r"(a[1]),"r"(a[2]),"r"(a[3]),"r"(b[0]),"r"(b[1]));
}
__device__ __forceinline__ void ldm_x4(uint32_t& r0,uint32_t& r1,uint32_t& r2,uint32_t& r3, const uint16_t* p){
    uint32_t a = smem_u32(p);
    asm volatile("ldmatrix.sync.aligned.m8n8.x4.shared.b16 {%0,%1,%2,%3},[%4];"
        : "=r"(r0),"=r"(r1),"=r"(r2),"=r"(r3) : "r"(a));
}
__device__ __forceinline__ void ldm_x4t(uint32_t& r0,uint32_t& r1,uint32_t& r2,uint32_t& r3, const uint16_t* p){
    uint32_t a = smem_u32(p);
    asm volatile("ldmatrix.sync.aligned.m8n8.x4.trans.shared.b16 {%0,%1,%2,%3},[%4];"
        : "=r"(r0),"=r"(r1),"=r"(r2),"=r"(r3) : "r"(a));
}

// ---------------- R3 GEMM core: 128x64, BK=16, fp16 hi/lo 3-term ----------------
template<bool TRANSB>
__device__ __forceinline__ void gemm_tc(const float* __restrict__ A, int lda,
                                        const float* __restrict__ B, int ldb,
                                        int K, int row0, int col0,
                                        float (*acc)[4])
{
    constexpr int BSTR = 64 + 8;
    constexpr int BS = TRANSB ? (64*BSTRH_NK) : (BKK*BSTR);

    __shared__ __align__(16) uint16_t As_hi[2][BM*ASTRH];
    __shared__ __align__(16) uint16_t As_lo[2][BM*ASTRH];
    __shared__ __align__(16) uint16_t Bs_hi[2][BS];
    __shared__ __align__(16) uint16_t Bs_lo[2][BS];

    int tid = threadIdx.x;
    int wid = tid >> 5, lane = tid & 31;
    int wm = wid >> 1, wn = wid & 1;

    int rA = tid >> 1, koA = (tid & 1)*8;
    int nB = tid >> 2, koB = (tid & 3)*4;
    int kB = tid >> 4, nqB = (tid & 15)*4;

    float4 a0r, a1r, b0r;
    auto ldg = [&](int it){
        int k0 = it*BKK;
        const float* ap = A + (size_t)(row0+rA)*lda + k0 + koA;
        a0r = *(const float4*)ap;
        a1r = *(const float4*)(ap+4);
        if (TRANSB) b0r = *(const float4*)(B + (size_t)(col0+nB)*ldb + k0 + koB);
        else        b0r = *(const float4*)(B + (size_t)(k0+kB)*ldb + col0 + nqB);
    };
    auto cvtstore = [&](int buf){
        uint32_t h0,h1,h2,h3,l0,l1,l2,l3;
        sp16(a0r.x,a0r.y,h0,l0); sp16(a0r.z,a0r.w,h1,l1);
        sp16(a1r.x,a1r.y,h2,l2); sp16(a1r.z,a1r.w,h3,l3);
        *(uint4*)&As_hi[buf][rA*ASTRH + koA] = make_uint4(h0,h1,h2,h3);
        *(uint4*)&As_lo[buf][rA*ASTRH + koA] = make_uint4(l0,l1,l2,l3);
        uint32_t bh0,bh1,bl0,bl1;
        sp16(b0r.x,b0r.y,bh0,bl0); sp16(b0r.z,b0r.w,bh1,bl1);
        if (TRANSB){
            *(uint2*)&Bs_hi[buf][nB*BSTRH_NK + koB] = make_uint2(bh0,bh1);
            *(uint2*)&Bs_lo[buf][nB*BSTRH_NK + koB] = make_uint2(bl0,bl1);
        } else {
            *(uint2*)&Bs_hi[buf][kB*BSTR + nqB] = make_uint2(bh0,bh1);
            *(uint2*)&Bs_lo[buf][kB*BSTR + nqB] = make_uint2(bl0,bl1);
        }
    };

    int nit = K / BKK;
    ldg(0); cvtstore(0);
    __syncthreads();
    int buf = 0;
    int aro = ((lane>>3)&1)*8 + (lane&7);
    int aco = (lane>>4)*8;
    #pragma unroll 1
    for (int it=0; it<nit; it++){
        bool more = (it+1 < nit);
        if (more) ldg(it+1);

        uint32_t ah[2][4], al[2][4];
        #pragma unroll
        for (int mt=0; mt<2; mt++){
            int mbase = wm*32 + mt*16;
            ldm_x4(ah[mt][0],ah[mt][1],ah[mt][2],ah[mt][3], &As_hi[buf][(mbase+aro)*ASTRH + aco]);
            ldm_x4(al[mt][0],al[mt][1],al[mt][2],al[mt][3], &As_lo[buf][(mbase+aro)*ASTRH + aco]);
        }
        uint32_t bh[4][2], bl[4][2];
        #pragma unroll
        for (int np=0; np<2; np++){
            int nbase = wn*32 + np*16;
            uint32_t r0,r1,r2,r3;
            if (TRANSB){
                int nrow = nbase + (lane>>4)*8 + (lane&7);
                int kcol = ((lane>>3)&1)*8;
                ldm_x4(r0,r1,r2,r3, &Bs_hi[buf][nrow*BSTRH_NK + kcol]);
                bh[np*2][0]=r0; bh[np*2][1]=r1; bh[np*2+1][0]=r2; bh[np*2+1][1]=r3;
                ldm_x4(r0,r1,r2,r3, &Bs_lo[buf][nrow*BSTRH_NK + kcol]);
                bl[np*2][0]=r0; bl[np*2][1]=r1; bl[np*2+1][0]=r2; bl[np*2+1][1]=r3;
            } else {
                int krow = ((lane>>3)&1)*8 + (lane&7);
                int ncol = nbase + (lane>>4)*8;
                ldm_x4t(r0,r1,r2,r3, &Bs_hi[buf][krow*BSTR + ncol]);
                bh[np*2][0]=r0; bh[np*2][1]=r1; bh[np*2+1][0]=r2; bh[np*2+1][1]=r3;
                ldm_x4t(r0,r1,r2,r3, &Bs_lo[buf][krow*BSTR + ncol]);
                bl[np*2][0]=r0; bl[np*2][1]=r1; bl[np*2+1][0]=r2; bl[np*2+1][1]=r3;
            }
        }
        #pragma unroll
        for (int mt=0; mt<2; mt++)
            #pragma unroll
            for (int nt=0; nt<4; nt++){
                mma_f16r(acc[mt*4+nt], ah[mt], bh[nt]);
                mma_f16r(acc[mt*4+nt], al[mt], bh[nt]);
                mma_f16r(acc[mt*4+nt], ah[mt], bl[nt]);
            }

        if (more) cvtstore(buf^1);
        __syncthreads();
        buf ^= 1;
    }
}

#define EPI_BEGIN { \
    int lane = threadIdx.x & 31, wid_ = threadIdx.x >> 5; \
    int wm = wid_ >> 1, wn = wid_ & 1, g = lane >> 2, t = lane & 3; \
    _Pragma("unroll") \
    for (int mt=0; mt<2; mt++) \
    _Pragma("unroll") \
    for (int nt=0; nt<4; nt++) \
    _Pragma("unroll") \
    for (int h2=0; h2<2; h2++){ \
        int rr = row0 + wm*32 + mt*16 + g + h2*8; \
        int cc = col0 + wn*32 + nt*8 + 2*t; \
        float v0 = acc[mt*4+nt][h2*2]; \
        float v1 = acc[mt*4+nt][h2*2+1];
#define EPI_END }}

// ---------------- routing (+ source pointer table) ----------------
__global__ void k_route(const float* __restrict__ node_p, const float* __restrict__ edge_p,
                        const float* inpute, const float* inputo){
    if (threadIdx.x != 0 || blockIdx.x != 0) return;
    g_srcp[0] = inpute;
    g_srcp[1] = inputo;
    for (int i = 0; i < 8; i++) g_srcp[2+i] = g_outs[2+i];
    bool processed[8];
    for (int i=0;i<8;i++) processed[i]=false;
    int lind = 0;
    for (int c=0;c<8;c++){
        int nsrc = (c+2 < 5) ? (c+2) : 5;
        int snode = c - nsrc;
        int L = nsrc*5;
        const float* npc = node_p + c*8;
        int act = 0; float bm = npc[0];
        for (int i=1;i<8;i++) if (npc[i] > bm){ bm=npc[i]; act=i; }
        float ssum = 0.0f;
        for (int i=0;i<8;i++) ssum += expf(npc[i]-bm);
        float aw = expf(npc[act]-bm)/ssum;

        Route r; r.act=act; r.aw=aw;
        for (int z=0;z<3;z++){ r.has[z]=0; r.op[z]=0; r.src[z]=0; r.edge[z]=0; r.w[z]=0.0f; }

        #define EPV(i,j) edge_p[((i)*NEDGE_ + lind + (j)/5)*5 + ((j)%5)]

        int qs = 5; float qbm = EPV(0,5);
        for (int j=6;j<L;j++){ float v=EPV(0,j); if (v>qbm){qbm=v;qs=j;} }
        float qsum = 0.0f;
        for (int j=5;j<L;j++) qsum += expf(EPV(0,j)-qbm);
        {
            int se = qs/5;
            r.op[0]=qs%5; r.src[0]=(se==0)?0:(snode+se+2); r.edge[0]=lind+se; r.w[0]=1.0f/qsum; r.has[0]=1;
            if (r.src[0]>=2) processed[r.src[0]-2]=true;
        }
        if (act < 7){
            int lo = (act>0) ? 5 : 0;
            int ks = lo; float kbm = EPV(1,lo);
            for (int j=lo+1;j<L;j++){ float v=EPV(1,j); if (v>kbm){kbm=v;ks=j;} }
            float ksum = 0.0f;
            for (int j=lo;j<L;j++) ksum += expf(EPV(1,j)-kbm);
            {
                int se = ks/5;
                r.op[1]=ks%5; r.src[1]=(se==0)?0:(snode+se+2); r.edge[1]=lind+se; r.w[1]=1.0f/ksum; r.has[1]=1;
                if (r.src[1]>=2) processed[r.src[1]-2]=true;
            }
            if (act < 5){
                int vs; float vw;
                if (act==0 && ks<5){
                    vs = 0; float vbm = EPV(2,0);
                    for (int j=1;j<5;j++){ float v=EPV(2,j); if (v>vbm){vbm=v;vs=j;} }
                    float vsum=0.0f;
                    for (int j=0;j<5;j++) vsum += expf(EPV(2,j)-vbm);
                    vw = 1.0f/vsum;
                } else {
                    vs = lo; float vbm = EPV(2,lo);
                    for (int j=lo+1;j<L;j++){ float v=EPV(2,j); if (v>vbm){vbm=v;vs=j;} }
                    float vsum=0.0f;
                    for (int j=lo;j<L;j++) vsum += expf(EPV(2,j)-vbm);
                    vw = 1.0f/vsum;
                }
                int se = vs/5;
                r.op[2]=vs%5; r.src[2]=(se==0)?0:(snode+se+2); r.edge[2]=lind+se; r.w[2]=vw; r.has[2]=1;
                if (r.src[2]>=2) processed[r.src[2]-2]=true;
            }
        }
        #undef EPV
        g_routes[c] = r;
        lind += nsrc;
    }
    for (int i=0;i<8;i++) g_rem[i] = processed[i]?0:1;
}

// ---------------- edge prep: warp-per-row LN / identity (8 rows per block) ----------------
__global__ void k_edge_prep(int c, const float* __restrict__ eg, const float* __restrict__ ebeta){
    int z = blockIdx.z;
    if (!g_routes[c].has[z]) return;
    int op = g_routes[c].op[z];
    if (op == 3) return;
    int w = threadIdx.x >> 5, lane = threadIdx.x & 31;
    int row = blockIdx.x*8 + w;
    const float4* x = (const float4*)(g_srcp[g_routes[c].src[z]] + (size_t)row*DIM);
    float4 v[4];
    #pragma unroll
    for (int j=0;j<4;j++) v[j] = x[lane + 32*j];
    if (op == 4){
        float ww = g_routes[c].w[z];
        float4* o = (float4*)(g_qkv[z] + (size_t)row*DIM);
        #pragma unroll
        for (int j=0;j<4;j++) o[lane + 32*j] = make_float4(ww*v[j].x, ww*v[j].y, ww*v[j].z, ww*v[j].w);
        return;
    }
    float s = 0.f, q = 0.f;
    #pragma unroll
    for (int j=0;j<4;j++){
        s += v[j].x+v[j].y+v[j].z+v[j].w;
        q += v[j].x*v[j].x+v[j].y*v[j].y+v[j].z*v[j].z+v[j].w*v[j].w;
    }
    #pragma unroll
    for (int o2=16;o2>0;o2>>=1){
        s += __shfl_xor_sync(0xFFFFFFFFu, s, o2);
        q += __shfl_xor_sync(0xFFFFFFFFu, q, o2);
    }
    float mean = s*(1.0f/DIM);
    float rstd = rsqrtf(q*(1.0f/DIM) - mean*mean + 1e-6f);
    int e = g_routes[c].edge[z];
    const float4* gg = (const float4*)(eg    + (size_t)e*DIM);
    const float4* bb = (const float4*)(ebeta + (size_t)e*DIM);
    float4* o = (float4*)(g_eln[z] + (size_t)row*DIM);
    #pragma unroll
    for (int j=0;j<4;j++){
        float4 g4 = gg[lane + 32*j], b4 = bb[lane + 32*j];
        float4 r;
        r.x=(v[j].x-mean)*rstd*g4.x+b4.x; r.y=(v[j].y-mean)*rstd*g4.y+b4.y;
        r.z=(v[j].z-mean)*rstd*g4.z+b4.z; r.w=(v[j].w-mean)*rstd*g4.w+b4.w;
        o[lane + 32*j] = r;
    }
}

// ---------------- edge GEMM ----------------
__global__ void __launch_bounds__(256) k_edge_gemm(int c, const float* __restrict__ eW, const float* __restrict__ eb){
    int z = blockIdx.z;
    if (!g_routes[c].has[z]) return;
    int op = g_routes[c].op[z];
    if (op == 4) return;
    int e = g_routes[c].edge[z];
    const float* A = (op <= 2) ? g_eln[z] : g_srcp[g_routes[c].src[z]];
    const float* W = eW + (size_t)e*DIM*DIM;
    int row0 = blockIdx.y*BM, col0 = blockIdx.x*64;
    float acc[8][4] = {};
    gemm_tc<false>(A, DIM, W, DIM, DIM, row0, col0, acc);
    float w = g_routes[c].w[z];
    const float* bias = eb + (size_t)e*DIM;
    EPI_BEGIN
        v0 += bias[cc]; v1 += bias[cc+1];
        if (op==0){ v0=fmaxf(v0,0.f); v1=fmaxf(v1,0.f); }
        else if (op==1){ v0=geluf(v0); v1=geluf(v1); }
        *(float2*)&g_qkv[z][(size_t)rr*DIM + cc] = make_float2(w*v0, w*v1);
    EPI_END
}

// ---------------- node LN (act 0; warp-per-row, 8 rows per block) ----------------
__global__ void k_node_ln(int c, const float* __restrict__ ng, const float* __restrict__ nbeta){
    if (g_routes[c].act != 0) return;
    int w = threadIdx.x >> 5, lane = threadIdx.x & 31;
    int row = blockIdx.x*8 + w;
    const float4* x = (const float4*)(g_qkv[0] + (size_t)row*DIM);
    float4 v[4];
    #pragma unroll
    for (int j=0;j<4;j++) v[j] = x[lane + 32*j];
    float s = 0.f, q = 0.f;
    #pragma unroll
    for (int j=0;j<4;j++){
        s += v[j].x+v[j].y+v[j].z+v[j].w;
        q += v[j].x*v[j].x+v[j].y*v[j].y+v[j].z*v[j].z+v[j].w*v[j].w;
    }
    #pragma unroll
    for (int o2=16;o2>0;o2>>=1){
        s += __shfl_xor_sync(0xFFFFFFFFu, s, o2);
        q += __shfl_xor_sync(0xFFFFFFFFu, q, o2);
    }
    float mean = s*(1.0f/DIM);
    float rstd = rsqrtf(q*(1.0f/DIM) - mean*mean + 1e-6f);
    const float4* gg = (const float4*)(ng    + (size_t)c*DIM);
    const float4* bb = (const float4*)(nbeta + (size_t)c*DIM);
    float4* o = (float4*)(g_ln + (size_t)row*DIM);
    #pragma unroll
    for (int j=0;j<4;j++){
        float4 g4 = gg[lane + 32*j], b4 = bb[lane + 32*j];
        float4 r;
        r.x=(v[j].x-mean)*rstd*g4.x+b4.x; r.y=(v[j].y-mean)*rstd*g4.y+b4.y;
        r.z=(v[j].z-mean)*rstd*g4.z+b4.z; r.w=(v[j].w-mean)*rstd*g4.w+b4.w;
        o[lane + 32*j] = r;
    }
}

// ---------------- node GEMMs W0/W1/W2 ----------------
__global__ void __launch_bounds__(256) k_node_gemm123(int c, const float* __restrict__ nW, const float* __restrict__ nb){
    int act = g_routes[c].act;
    int z = blockIdx.z;
    const float* A; bool need, bias; int actf = 0;
    if (z == 0){
        need = (act==0||act==1||act==3);
        A = (act==0) ? g_ln : g_qkv[0];
        bias = (act!=3); actf = (act==1)?1:0;
    } else if (z == 1){
        need = (act==0||act==1||act==3||act==5);
        A = g_qkv[1];
        bias = (act!=3); actf = (act==5)?1:0;
    } else {
        need = (act==0||act==3);
        A = g_qkv[2];
        bias = (act==0);
    }
    if (!need) return;
    const float* W = nW + ((size_t)c*4 + z)*DIM*DIM;
    int row0 = blockIdx.y*BM, col0 = blockIdx.x*64;
    float acc[8][4] = {};
    gemm_tc<false>(A, DIM, W, DIM, DIM, row0, col0, acc);
    const float* bp = nb + ((size_t)c*4 + z)*DIM;
    EPI_BEGIN
        if (bias){ v0 += bp[cc]; v1 += bp[cc+1]; }
        if (actf){ v0 = geluf(v0); v1 = geluf(v1); }
        *(float2*)&g_t[z][(size_t)rr*DIM + cc] = make_float2(v0, v1);
    EPI_END
}

// ---------------- elementwise mid (512 blocks) ----------------
__global__ void k_node_mid(int c){
    int act = g_routes[c].act;
    if (act != 1 && act != 3) return;
    #pragma unroll
    for (int j=0;j<4;j++){
        size_t i = (size_t)blockIdx.x*1024 + j*256 + threadIdx.x;
        float4 a = ((const float4*)g_t[0])[i];
        float4 b = ((const float4*)g_t[1])[i];
        float4 o;
        if (act == 1){
            o = make_float4(a.x*b.x, a.y*b.y, a.z*b.z, a.w*b.w);
        } else {
            float4 d = ((const float4*)g_t[2])[i];
            o = make_float4(fmaxf(a.x+b.x+d.x,0.f), fmaxf(a.y+b.y+d.y,0.f),
                            fmaxf(a.z+b.z+d.z,0.f), fmaxf(a.w+b.w+d.w,0.f));
        }
        ((float4*)g_t[3])[i] = o;
    }
}

// ---------------- attention ----------------
__global__ void __launch_bounds__(256) k_attn_scores(int c){
    if (g_routes[c].act != 0) return;
    int bz = blockIdx.z, b = bz >> 3, h = bz & 7;
    const float* A  = g_t[0] + (size_t)b*SLEN_*DIM + h*DH;
    const float* Bp = g_t[1] + (size_t)b*SLEN_*DIM + h*DH;
    int row0 = blockIdx.y*BM, col0 = blockIdx.x*64;
    float acc[8][4] = {};
    gemm_tc<true>(A, DIM, Bp, DIM, DH, row0, col0, acc);
    float* S = g_scores + (size_t)bz*SLEN_*SLEN_;
    EPI_BEGIN
        *(float2*)&S[(size_t)rr*SLEN_ + cc] = make_float2(v0*0.125f, v1*0.125f);
    EPI_END
}

// softmax: 32 rows per block, warp-per-row (grid 32 x 32)
__global__ void k_attn_softmax(int c){
    if (g_routes[c].act != 0) return;
    int bz = blockIdx.y;
    int w = threadIdx.x >> 5, lane = threadIdx.x & 31;
    #pragma unroll 1
    for (int rr = w; rr < 32; rr += 8){
        int row = blockIdx.x*32 + rr;
        float4* p = (float4*)(g_scores + ((size_t)bz*SLEN_ + row)*SLEN_);
        float4 v[8];
        float m = -1e30f;
        #pragma unroll
        for (int j=0;j<8;j++){
            v[j] = p[lane + 32*j];
            m = fmaxf(m, fmaxf(fmaxf(v[j].x,v[j].y), fmaxf(v[j].z,v[j].w)));
        }
        #pragma unroll
        for (int o=16;o>0;o>>=1) m = fmaxf(m, __shfl_xor_sync(0xFFFFFFFFu, m, o));
        float s = 0.f;
        #pragma unroll
        for (int j=0;j<8;j++){
            v[j].x=expf(v[j].x-m); v[j].y=expf(v[j].y-m);
            v[j].z=expf(v[j].z-m); v[j].w=expf(v[j].w-m);
            s += v[j].x+v[j].y+v[j].z+v[j].w;
        }
        #pragma unroll
        for (int o=16;o>0;o>>=1) s += __shfl_xor_sync(0xFFFFFFFFu, s, o);
        float inv = 1.0f/s;
        #pragma unroll
        for (int j=0;j<8;j++){
            v[j].x*=inv; v[j].y*=inv; v[j].z*=inv; v[j].w*=inv;
            p[lane + 32*j] = v[j];
        }
    }
}

__global__ void __launch_bounds__(256) k_attn_av(int c){
    if (g_routes[c].act != 0) return;
    int bz = blockIdx.z, b = bz >> 3, h = bz & 7;
    const float* A  = g_scores + (size_t)bz*SLEN_*SLEN_;
    const float* Bp = g_t[2] + (size_t)b*SLEN_*DIM + h*DH;
    int row0 = blockIdx.y*BM, col0 = 0;
    float acc[8][4] = {};
    gemm_tc<false>(A, SLEN_, Bp, DIM, SLEN_, row0, col0, acc);
    EPI_BEGIN
        *(float2*)&g_t[3][(size_t)(b*SLEN_ + rr)*DIM + h*DH + cc] = make_float2(v0, v1);
    EPI_END
}

// ---------------- node GEMM W3 (fused residual + aw -> g_outs) ----------------
__global__ void __launch_bounds__(256) k_node_gemm4(int c, const float* __restrict__ nW, const float* __restrict__ nb){
    int act = g_routes[c].act;
    if (!(act==0||act==1||act==3)) return;
    const float* W = nW + ((size_t)c*4 + 3)*DIM*DIM;
    int row0 = blockIdx.y*BM, col0 = blockIdx.x*64;
    float acc[8][4] = {};
    gemm_tc<false>(g_t[3], DIM, W, DIM, DIM, row0, col0, acc);
    const float* bp = nb + ((size_t)c*4 + 3)*DIM;
    float aw = g_routes[c].aw;
    float* outp = g_outs[2+c];
    EPI_BEGIN
        float2 q = *(const float2*)&g_qkv[0][(size_t)rr*DIM + cc];
        *(float2*)&outp[(size_t)rr*DIM + cc] =
            make_float2(aw*(q.x + v0 + bp[cc]), aw*(q.y + v1 + bp[cc+1]));
    EPI_END
}

// ---------------- node finalize (acts 2,4,5,6,7 only; warp-per-row) ----------------
__global__ void k_node_final(int c, const float* __restrict__ ng, const float* __restrict__ nbeta){
    int act = g_routes[c].act;
    if (act==0 || act==1 || act==3) return;   // fused into gemm4
    float aw = g_routes[c].aw;
    int w = threadIdx.x >> 5, lane = threadIdx.x & 31;
    int row = blockIdx.x*8 + w;
    size_t off = (size_t)row*DIM;
    const float4* qp = (const float4*)(g_qkv[0] + off);
    float4 q[4];
    #pragma unroll
    for (int j=0;j<4;j++) q[j] = qp[lane + 32*j];
    float4 o[4];
    bool needln = false;
    float4 x[4];
    if (act==5){
        const float4* tp = (const float4*)(g_t[1] + off);
        #pragma unroll
        for (int j=0;j<4;j++){
            float4 t1 = tp[lane + 32*j];
            o[j] = make_float4(q[j].x+t1.x, q[j].y+t1.y, q[j].z+t1.z, q[j].w+t1.w);
        }
    } else if (act==2){
        const float4* kp = (const float4*)(g_qkv[1] + off);
        const float4* vp = (const float4*)(g_qkv[2] + off);
        #pragma unroll
        for (int j=0;j<4;j++){
            float4 k = kp[lane + 32*j], v = vp[lane + 32*j];
            x[j] = make_float4(q[j].x+k.x+v.x, q[j].y+k.y+v.y, q[j].z+k.z+v.z, q[j].w+k.w+v.w);
        }
        needln = true;
    } else if (act==4){
        const float4* kp = (const float4*)(g_qkv[1] + off);
        const float4* vp = (const float4*)(g_qkv[2] + off);
        #pragma unroll
        for (int j=0;j<4;j++){
            float4 k = kp[lane + 32*j], v = vp[lane + 32*j];
            o[j] = make_float4(q[j].x*sigm(k.x)+v.x, q[j].y*sigm(k.y)+v.y,
                               q[j].z*sigm(k.z)+v.z, q[j].w*sigm(k.w)+v.w);
        }
    } else if (act==6){
        const float4* kp = (const float4*)(g_qkv[1] + off);
        #pragma unroll
        for (int j=0;j<4;j++){
            float4 k = kp[lane + 32*j];
            o[j] = make_float4(q[j].x+k.x, q[j].y+k.y, q[j].z+k.z, q[j].w+k.w);
        }
    } else { // act 7
        #pragma unroll
        for (int j=0;j<4;j++) x[j] = q[j];
        needln = true;
    }
    if (needln){
        float s = 0.f, qq = 0.f;
        #pragma unroll
        for (int j=0;j<4;j++){
            s += x[j].x+x[j].y+x[j].z+x[j].w;
            qq += x[j].x*x[j].x+x[j].y*x[j].y+x[j].z*x[j].z+x[j].w*x[j].w;
        }
        #pragma unroll
        for (int o2=16;o2>0;o2>>=1){
            s += __shfl_xor_sync(0xFFFFFFFFu, s, o2);
            qq += __shfl_xor_sync(0xFFFFFFFFu, qq, o2);
        }
        float mean = s*(1.0f/DIM);
        float rstd = rsqrtf(qq*(1.0f/DIM) - mean*mean + 1e-6f);
        const float4* gg = (const float4*)(ng    + (size_t)c*DIM);
        const float4* bb = (const float4*)(nbeta + (size_t)c*DIM);
        #pragma unroll
        for (int j=0;j<4;j++){
            float4 g4 = gg[lane + 32*j], b4 = bb[lane + 32*j];
            o[j].x=(x[j].x-mean)*rstd*g4.x+b4.x; o[j].y=(x[j].y-mean)*rstd*g4.y+b4.y;
            o[j].z=(x[j].z-mean)*rstd*g4.z+b4.z; o[j].w=(x[j].w-mean)*rstd*g4.w+b4.w;
        }
    }
    float4* op = (float4*)(g_outs[2+c] + off);
    #pragma unroll
    for (int j=0;j<4;j++){
        o[j].x*=aw; o[j].y*=aw; o[j].z*=aw; o[j].w*=aw;
        op[lane + 32*j] = o[j];
    }
}

// ---------------- final sum + LN (warp-per-row) ----------------
__global__ void k_final(const float* __restrict__ og, const float* __restrict__ ob, float* __restrict__ out){
    int w = threadIdx.x >> 5, lane = threadIdx.x & 31;
    int row = blockIdx.x*8 + w;
    size_t off = (size_t)row*DIM;
    float4 s4[4];
    #pragma unroll
    for (int j=0;j<4;j++) s4[j] = make_float4(0.f,0.f,0.f,0.f);
    #pragma unroll
    for (int n=0;n<8;n++){
        if (g_rem[n]){
            const float4* vp = (const float4*)(g_outs[2+n] + off);
            #pragma unroll
            for (int j=0;j<4;j++){
                float4 v = vp[lane + 32*j];
                s4[j].x+=v.x; s4[j].y+=v.y; s4[j].z+=v.z; s4[j].w+=v.w;
            }
        }
    }
    float s = 0.f, q = 0.f;
    #pragma unroll
    for (int j=0;j<4;j++){
        s += s4[j].x+s4[j].y+s4[j].z+s4[j].w;
        q += s4[j].x*s4[j].x+s4[j].y*s4[j].y+s4[j].z*s4[j].z+s4[j].w*s4[j].w;
    }
    #pragma unroll
    for (int o2=16;o2>0;o2>>=1){
        s += __shfl_xor_sync(0xFFFFFFFFu, s, o2);
        q += __shfl_xor_sync(0xFFFFFFFFu, q, o2);
    }
    float mean = s*(1.0f/DIM);
    float rstd = rsqrtf(q*(1.0f/DIM) - mean*mean + 1e-6f);
    const float4* gg = (const float4*)og;
    const float4* bb = (const float4*)ob;
    float4* op = (float4*)(out + off);
    #pragma unroll
    for (int j=0;j<4;j++){
        float4 g4 = gg[lane + 32*j], b4 = bb[lane + 32*j];
        float4 o;
        o.x=(s4[j].x-mean)*rstd*g4.x+b4.x; o.y=(s4[j].y-mean)*rstd*g4.y+b4.y;
        o.z=(s4[j].z-mean)*rstd*g4.z+b4.z; o.w=(s4[j].w-mean)*rstd*g4.w+b4.w;
        op[lane + 32*j] = o;
    }
}

// ---------------- launch ----------------
extern "C" void kernel_launch(void* const* d_in, const int* in_sizes, int n_in,
                              void* d_out, int out_size)
{
    const float* inpute    = (const float*)d_in[0];
    const float* inputo    = (const float*)d_in[1];
    const float* node_p    = (const float*)d_in[2];
    const float* edge_p    = (const float*)d_in[3];
    const float* edge_W    = (const float*)d_in[4];
    const float* edge_b    = (const float*)d_in[5];
    const float* edge_g    = (const float*)d_in[6];
    const float* edge_beta = (const float*)d_in[7];
    const float* node_W    = (const float*)d_in[8];
    const float* node_b    = (const float*)d_in[9];
    const float* node_g    = (const float*)d_in[10];
    const float* node_beta = (const float*)d_in[11];
    const float* out_g     = (const float*)d_in[12];
    const float* out_beta  = (const float*)d_in[13];
    float* out = (float*)d_out;

    k_route<<<1, 32>>>(node_p, edge_p, inpute, inputo);

    for (int c = 0; c < 8; c++){
        k_edge_prep<<<dim3(NROW/8,1,3), 256>>>(c, edge_g, edge_beta);
        k_edge_gemm<<<dim3(DIM/64, NROW/BM, 3), 256>>>(c, edge_W, edge_b);
        k_node_ln<<<NROW/8, 256>>>(c, node_g, node_beta);
        k_node_gemm123<<<dim3(DIM/64, NROW/BM, 3), 256>>>(c, node_W, node_b);
        k_node_mid<<<NMELEM/4/1024, 256>>>(c);
        k_attn_scores<<<dim3(SLEN_/64, SLEN_/BM, 32), 256>>>(c);
        k_attn_softmax<<<dim3(SLEN_/32, 32), 256>>>(c);
        k_attn_av<<<dim3(1, SLEN_/BM, 32), 256>>>(c);
        k_node_gemm4<<<dim3(DIM/64, NROW/BM), 256>>>(c, node_W, node_b);
        k_node_final<<<NROW/8, 256>>>(c, node_g, node_beta);
    }
    k_final<<<NROW/8, 256>>>(out_g, out_beta, out);
}

// round 14
// speedup vs baseline: 1.0468x; 1.0054x over previous
#include <cuda_runtime.h>
#include <cuda_fp16.h>
#include <math.h>
#include <stdint.h>

// ---------------- constants ----------------
#define NROW 4096
#define DIM  512
#define SLEN_ 1024
#define DH 64
#define NMELEM (NROW*DIM)
#define NEDGE_ 34

#define BM 128
#define BKK 16
#define ASTRH 24
#define BSTRH_NK 24

// BK=32 weight-GEMM smem layout (halfs)
#define W_ASTR 40
#define W_BSTR 72
#define W_ABUF (128*W_ASTR)      // 5120
#define W_BBUF (32*W_BSTR)       // 2304
#define W_SMEM ((2*W_ABUF*2 + 2*W_BBUF*2)*2)   // 59392 bytes

struct Route {
    int   act;
    float aw;
    int   op[3];
    int   src[3];
    int   edge[3];
    float w[3];
    int   has[3];
};

// ---------------- device globals ----------------
__device__ __align__(16) float g_outs[10][NMELEM];
__device__ __align__(16) float g_eln[3][NMELEM];
__device__ __align__(16) float g_qkv[3][NMELEM];
__device__ __align__(16) float g_ln[NMELEM];
__device__ __align__(16) float g_t[4][NMELEM];
__device__ __align__(16) float g_scores[(size_t)32*SLEN_*SLEN_];
__device__ const float* g_srcp[10];
__device__ Route g_routes[8];
__device__ int   g_rem[8];

// ---------------- helpers ----------------
__device__ __forceinline__ float geluf(float x){
    float x3 = x*x*x;
    return 0.5f*x*(1.0f + tanhf(0.7978845608028654f*(x + 0.044715f*x3)));
}
__device__ __forceinline__ float sigm(float x){ return 1.0f/(1.0f+expf(-x)); }

__device__ __forceinline__ void sp16(float x0, float x1, uint32_t& h, uint32_t& l){
    __half2 hh = __floats2half2_rn(x0, x1);
    float2 hf = __half22float2(hh);
    __half2 ll = __floats2half2_rn(x0 - hf.x, x1 - hf.y);
    h = *(uint32_t*)&hh; l = *(uint32_t*)&ll;
}
__device__ __forceinline__ uint32_t smem_u32(const void* p){
    return (uint32_t)__cvta_generic_to_shared(p);
}
__device__ __forceinline__ void mma_f16r(float* c, const uint32_t* a, const uint32_t* b){
    asm volatile("mma.sync.aligned.m16n8k16.row.col.f32.f16.f16.f32 "
        "{%0,%1,%2,%3},{%4,%5,%6,%7},{%8,%9},{%0,%1,%2,%3};"
        : "+f"(c[0]),"+f"(c[1]),"+f"(c[2]),"+f"(c[3])
        : "r"(a[0]),"r"(a[1]),"r"(a[2]),"r"(a[3]),"r"(b[0]),"r"(b[1]));
}
__device__ __forceinline__ void ldm_x4(uint32_t& r0,uint32_t& r1,uint32_t& r2,uint32_t& r3, const uint16_t* p){
    uint32_t a = smem_u32(p);
    asm volatile("ldmatrix.sync.aligned.m8n8.x4.shared.b16 {%0,%1,%2,%3},[%4];"
        : "=r"(r0),"=r"(r1),"=r"(r2),"=r"(r3) : "r"(a));
}
__device__ __forceinline__ void ldm_x4t(uint32_t& r0,uint32_t& r1,uint32_t& r2,uint32_t& r3, const uint16_t* p){
    uint32_t a = smem_u32(p);
    asm volatile("ldmatrix.sync.aligned.m8n8.x4.trans.shared.b16 {%0,%1,%2,%3},[%4];"
        : "=r"(r0),"=r"(r1),"=r"(r2),"=r"(r3) : "r"(a));
}

// ---------------- BK=32 weight GEMM (dynamic smem) ----------------
__device__ __forceinline__ void gemm_w32(const float* __restrict__ A,
                                         const float* __restrict__ B,
                                         int row0, int col0, float (*acc)[4])
{
    extern __shared__ __align__(16) uint16_t dsm[];
    uint16_t* As_hi = dsm;
    uint16_t* As_lo = As_hi + 2*W_ABUF;
    uint16_t* Bs_hi = As_lo + 2*W_ABUF;
    uint16_t* Bs_lo = Bs_hi + 2*W_BBUF;

    int tid = threadIdx.x;
    int wid = tid >> 5, lane = tid & 31;
    int wm = wid >> 1, wn = wid & 1;

    int rA = tid >> 1, koA = (tid & 1)*16;
    int kB = tid >> 3, nqB = (tid & 7)*8;

    const float* arow = A + (size_t)(row0+rA)*DIM + koA;
    const float* brow = B + (size_t)kB*DIM + col0 + nqB;

    float4 a0r, a1r, a2r, a3r, b0r, b1r;
    auto ldg = [&](int it){
        int k0 = it*32;
        a0r = *(const float4*)(arow + k0);
        a1r = *(const float4*)(arow + k0 + 4);
        a2r = *(const float4*)(arow + k0 + 8);
        a3r = *(const float4*)(arow + k0 + 12);
        const float* bp = brow + (size_t)k0*DIM;
        b0r = *(const float4*)bp;
        b1r = *(const float4*)(bp + 4);
    };
    auto cvtstore = [&](int buf){
        uint32_t h0,h1,h2,h3,l0,l1,l2,l3;
        sp16(a0r.x,a0r.y,h0,l0); sp16(a0r.z,a0r.w,h1,l1);
        sp16(a1r.x,a1r.y,h2,l2); sp16(a1r.z,a1r.w,h3,l3);
        *(uint4*)&As_hi[buf*W_ABUF + rA*W_ASTR + koA] = make_uint4(h0,h1,h2,h3);
        *(uint4*)&As_lo[buf*W_ABUF + rA*W_ASTR + koA] = make_uint4(l0,l1,l2,l3);
        sp16(a2r.x,a2r.y,h0,l0); sp16(a2r.z,a2r.w,h1,l1);
        sp16(a3r.x,a3r.y,h2,l2); sp16(a3r.z,a3r.w,h3,l3);
        *(uint4*)&As_hi[buf*W_ABUF + rA*W_ASTR + koA + 8] = make_uint4(h0,h1,h2,h3);
        *(uint4*)&As_lo[buf*W_ABUF + rA*W_ASTR + koA + 8] = make_uint4(l0,l1,l2,l3);
        uint32_t bh0,bh1,bh2,bh3,bl0,bl1,bl2,bl3;
        sp16(b0r.x,b0r.y,bh0,bl0); sp16(b0r.z,b0r.w,bh1,bl1);
        sp16(b1r.x,b1r.y,bh2,bl2); sp16(b1r.z,b1r.w,bh3,bl3);
        *(uint4*)&Bs_hi[buf*W_BBUF + kB*W_BSTR + nqB] = make_uint4(bh0,bh1,bh2,bh3);
        *(uint4*)&Bs_lo[buf*W_BBUF + kB*W_BSTR + nqB] = make_uint4(bl0,bl1,bl2,bl3);
    };

    ldg(0); cvtstore(0);
    __syncthreads();
    int buf = 0;
    int aro = ((lane>>3)&1)*8 + (lane&7);
    int aco = (lane>>4)*8;
    int bkr = ((lane>>3)&1)*8 + (lane&7);
    int bnc0 = (lane>>4)*8;
    #pragma unroll 1
    for (int it=0; it<DIM/32; it++){
        bool more = (it+1 < DIM/32);
        if (more) ldg(it+1);

        #pragma unroll
        for (int ks=0; ks<32; ks+=16){
            uint32_t ah[2][4], al[2][4];
            #pragma unroll
            for (int mt=0; mt<2; mt++){
                int mbase = wm*32 + mt*16;
                ldm_x4(ah[mt][0],ah[mt][1],ah[mt][2],ah[mt][3],
                       &As_hi[buf*W_ABUF + (mbase+aro)*W_ASTR + aco + ks]);
                ldm_x4(al[mt][0],al[mt][1],al[mt][2],al[mt][3],
                       &As_lo[buf*W_ABUF + (mbase+aro)*W_ASTR + aco + ks]);
            }
            uint32_t bh[4][2], bl[4][2];
            #pragma unroll
            for (int np=0; np<2; np++){
                int krow = ks + bkr;
                int ncol = wn*32 + np*16 + bnc0;
                uint32_t r0,r1,r2,r3;
                ldm_x4t(r0,r1,r2,r3, &Bs_hi[buf*W_BBUF + krow*W_BSTR + ncol]);
                bh[np*2][0]=r0; bh[np*2][1]=r1; bh[np*2+1][0]=r2; bh[np*2+1][1]=r3;
                ldm_x4t(r0,r1,r2,r3, &Bs_lo[buf*W_BBUF + krow*W_BSTR + ncol]);
                bl[np*2][0]=r0; bl[np*2][1]=r1; bl[np*2+1][0]=r2; bl[np*2+1][1]=r3;
            }
            #pragma unroll
            for (int mt=0; mt<2; mt++)
                #pragma unroll
                for (int nt=0; nt<4; nt++){
                    mma_f16r(acc[mt*4+nt], ah[mt], bh[nt]);
                    mma_f16r(acc[mt*4+nt], al[mt], bh[nt]);
                    mma_f16r(acc[mt*4+nt], ah[mt], bl[nt]);
                }
        }

        if (more) cvtstore(buf^1);
        __syncthreads();
        buf ^= 1;
    }
}

// ---------------- attention GEMM (unchanged R3 core, static smem) ----------------
template<bool TRANSB>
__device__ __forceinline__ void gemm_tc(const float* __restrict__ A, int lda,
                                        const float* __restrict__ B, int ldb,
                                        int K, int row0, int col0,
                                        float (*acc)[4])
{
    constexpr int BSTR = 64 + 8;
    constexpr int BS = TRANSB ? (64*BSTRH_NK) : (BKK*BSTR);

    __shared__ __align__(16) uint16_t As_hi[2][BM*ASTRH];
    __shared__ __align__(16) uint16_t As_lo[2][BM*ASTRH];
    __shared__ __align__(16) uint16_t Bs_hi[2][BS];
    __shared__ __align__(16) uint16_t Bs_lo[2][BS];

    int tid = threadIdx.x;
    int wid = tid >> 5, lane = tid & 31;
    int wm = wid >> 1, wn = wid & 1;

    int rA = tid >> 1, koA = (tid & 1)*8;
    int nB = tid >> 2, koB = (tid & 3)*4;
    int kB = tid >> 4, nqB = (tid & 15)*4;

    float4 a0r, a1r, b0r;
    auto ldg = [&](int it){
        int k0 = it*BKK;
        const float* ap = A + (size_t)(row0+rA)*lda + k0 + koA;
        a0r = *(const float4*)ap;
        a1r = *(const float4*)(ap+4);
        if (TRANSB) b0r = *(const float4*)(B + (size_t)(col0+nB)*ldb + k0 + koB);
        else        b0r = *(const float4*)(B + (size_t)(k0+kB)*ldb + col0 + nqB);
    };
    auto cvtstore = [&](int buf){
        uint32_t h0,h1,h2,h3,l0,l1,l2,l3;
        sp16(a0r.x,a0r.y,h0,l0); sp16(a0r.z,a0r.w,h1,l1);
        sp16(a1r.x,a1r.y,h2,l2); sp16(a1r.z,a1r.w,h3,l3);
        *(uint4*)&As_hi[buf][rA*ASTRH + koA] = make_uint4(h0,h1,h2,h3);
        *(uint4*)&As_lo[buf][rA*ASTRH + koA] = make_uint4(l0,l1,l2,l3);
        uint32_t bh0,bh1,bl0,bl1;
        sp16(b0r.x,b0r.y,bh0,bl0); sp16(b0r.z,b0r.w,bh1,bl1);
        if (TRANSB){
            *(uint2*)&Bs_hi[buf][nB*BSTRH_NK + koB] = make_uint2(bh0,bh1);
            *(uint2*)&Bs_lo[buf][nB*BSTRH_NK + koB] = make_uint2(bl0,bl1);
        } else {
            *(uint2*)&Bs_hi[buf][kB*BSTR + nqB] = make_uint2(bh0,bh1);
            *(uint2*)&Bs_lo[buf][kB*BSTR + nqB] = make_uint2(bl0,bl1);
        }
    };

    int nit = K / BKK;
    ldg(0); cvtstore(0);
    __syncthreads();
    int buf = 0;
    int aro = ((lane>>3)&1)*8 + (lane&7);
    int aco = (lane>>4)*8;
    #pragma unroll 1
    for (int it=0; it<nit; it++){
        bool more = (it+1 < nit);
        if (more) ldg(it+1);

        uint32_t ah[2][4], al[2][4];
        #pragma unroll
        for (int mt=0; mt<2; mt++){
            int mbase = wm*32 + mt*16;
            ldm_x4(ah[mt][0],ah[mt][1],ah[mt][2],ah[mt][3], &As_hi[buf][(mbase+aro)*ASTRH + aco]);
            ldm_x4(al[mt][0],al[mt][1],al[mt][2],al[mt][3], &As_lo[buf][(mbase+aro)*ASTRH + aco]);
        }
        uint32_t bh[4][2], bl[4][2];
        #pragma unroll
        for (int np=0; np<2; np++){
            int nbase = wn*32 + np*16;
            uint32_t r0,r1,r2,r3;
            if (TRANSB){
                int nrow = nbase + (lane>>4)*8 + (lane&7);
                int kcol = ((lane>>3)&1)*8;
                ldm_x4(r0,r1,r2,r3, &Bs_hi[buf][nrow*BSTRH_NK + kcol]);
                bh[np*2][0]=r0; bh[np*2][1]=r1; bh[np*2+1][0]=r2; bh[np*2+1][1]=r3;
                ldm_x4(r0,r1,r2,r3, &Bs_lo[buf][nrow*BSTRH_NK + kcol]);
                bl[np*2][0]=r0; bl[np*2][1]=r1; bl[np*2+1][0]=r2; bl[np*2+1][1]=r3;
            } else {
                int krow = ((lane>>3)&1)*8 + (lane&7);
                int ncol = nbase + (lane>>4)*8;
                ldm_x4t(r0,r1,r2,r3, &Bs_hi[buf][krow*BSTR + ncol]);
                bh[np*2][0]=r0; bh[np*2][1]=r1; bh[np*2+1][0]=r2; bh[np*2+1][1]=r3;
                ldm_x4t(r0,r1,r2,r3, &Bs_lo[buf][krow*BSTR + ncol]);
                bl[np*2][0]=r0; bl[np*2][1]=r1; bl[np*2+1][0]=r2; bl[np*2+1][1]=r3;
            }
        }
        #pragma unroll
        for (int mt=0; mt<2; mt++)
            #pragma unroll
            for (int nt=0; nt<4; nt++){
                mma_f16r(acc[mt*4+nt], ah[mt], bh[nt]);
                mma_f16r(acc[mt*4+nt], al[mt], bh[nt]);
                mma_f16r(acc[mt*4+nt], ah[mt], bl[nt]);
            }

        if (more) cvtstore(buf^1);
        __syncthreads();
        buf ^= 1;
    }
}

#define EPI_BEGIN { \
    int lane = threadIdx.x & 31, wid_ = threadIdx.x >> 5; \
    int wm = wid_ >> 1, wn = wid_ & 1, g = lane >> 2, t = lane & 3; \
    _Pragma("unroll") \
    for (int mt=0; mt<2; mt++) \
    _Pragma("unroll") \
    for (int nt=0; nt<4; nt++) \
    _Pragma("unroll") \
    for (int h2=0; h2<2; h2++){ \
        int rr = row0 + wm*32 + mt*16 + g + h2*8; \
        int cc = col0 + wn*32 + nt*8 + 2*t; \
        float v0 = acc[mt*4+nt][h2*2]; \
        float v1 = acc[mt*4+nt][h2*2+1];
#define EPI_END }}

// ---------------- routing (+ source pointer table) ----------------
__global__ void k_route(const float* __restrict__ node_p, const float* __restrict__ edge_p,
                        const float* inpute, const float* inputo){
    if (threadIdx.x != 0 || blockIdx.x != 0) return;
    g_srcp[0] = inpute;
    g_srcp[1] = inputo;
    for (int i = 0; i < 8; i++) g_srcp[2+i] = g_outs[2+i];
    bool processed[8];
    for (int i=0;i<8;i++) processed[i]=false;
    int lind = 0;
    for (int c=0;c<8;c++){
        int nsrc = (c+2 < 5) ? (c+2) : 5;
        int snode = c - nsrc;
        int L = nsrc*5;
        const float* npc = node_p + c*8;
        int act = 0; float bm = npc[0];
        for (int i=1;i<8;i++) if (npc[i] > bm){ bm=npc[i]; act=i; }
        float ssum = 0.0f;
        for (int i=0;i<8;i++) ssum += expf(npc[i]-bm);
        float aw = expf(npc[act]-bm)/ssum;

        Route r; r.act=act; r.aw=aw;
        for (int z=0;z<3;z++){ r.has[z]=0; r.op[z]=0; r.src[z]=0; r.edge[z]=0; r.w[z]=0.0f; }

        #define EPV(i,j) edge_p[((i)*NEDGE_ + lind + (j)/5)*5 + ((j)%5)]

        int qs = 5; float qbm = EPV(0,5);
        for (int j=6;j<L;j++){ float v=EPV(0,j); if (v>qbm){qbm=v;qs=j;} }
        float qsum = 0.0f;
        for (int j=5;j<L;j++) qsum += expf(EPV(0,j)-qbm);
        {
            int se = qs/5;
            r.op[0]=qs%5; r.src[0]=(se==0)?0:(snode+se+2); r.edge[0]=lind+se; r.w[0]=1.0f/qsum; r.has[0]=1;
            if (r.src[0]>=2) processed[r.src[0]-2]=true;
        }
        if (act < 7){
            int lo = (act>0) ? 5 : 0;
            int ks = lo; float kbm = EPV(1,lo);
            for (int j=lo+1;j<L;j++){ float v=EPV(1,j); if (v>kbm){kbm=v;ks=j;} }
            float ksum = 0.0f;
            for (int j=lo;j<L;j++) ksum += expf(EPV(1,j)-kbm);
            {
                int se = ks/5;
                r.op[1]=ks%5; r.src[1]=(se==0)?0:(snode+se+2); r.edge[1]=lind+se; r.w[1]=1.0f/ksum; r.has[1]=1;
                if (r.src[1]>=2) processed[r.src[1]-2]=true;
            }
            if (act < 5){
                int vs; float vw;
                if (act==0 && ks<5){
                    vs = 0; float vbm = EPV(2,0);
                    for (int j=1;j<5;j++){ float v=EPV(2,j); if (v>vbm){vbm=v;vs=j;} }
                    float vsum=0.0f;
                    for (int j=0;j<5;j++) vsum += expf(EPV(2,j)-vbm);
                    vw = 1.0f/vsum;
                } else {
                    vs = lo; float vbm = EPV(2,lo);
                    for (int j=lo+1;j<L;j++){ float v=EPV(2,j); if (v>vbm){vbm=v;vs=j;} }
                    float vsum=0.0f;
                    for (int j=lo;j<L;j++) vsum += expf(EPV(2,j)-vbm);
                    vw = 1.0f/vsum;
                }
                int se = vs/5;
                r.op[2]=vs%5; r.src[2]=(se==0)?0:(snode+se+2); r.edge[2]=lind+se; r.w[2]=vw; r.has[2]=1;
                if (r.src[2]>=2) processed[r.src[2]-2]=true;
            }
        }
        #undef EPV
        g_routes[c] = r;
        lind += nsrc;
    }
    for (int i=0;i<8;i++) g_rem[i] = processed[i]?0:1;
}

// ---------------- edge prep: warp-per-row LN / identity ----------------
__global__ void k_edge_prep(int c, const float* __restrict__ eg, const float* __restrict__ ebeta){
    int z = blockIdx.z;
    if (!g_routes[c].has[z]) return;
    int op = g_routes[c].op[z];
    if (op == 3) return;
    int w = threadIdx.x >> 5, lane = threadIdx.x & 31;
    int row = blockIdx.x*8 + w;
    const float4* x = (const float4*)(g_srcp[g_routes[c].src[z]] + (size_t)row*DIM);
    float4 v[4];
    #pragma unroll
    for (int j=0;j<4;j++) v[j] = x[lane + 32*j];
    if (op == 4){
        float ww = g_routes[c].w[z];
        float4* o = (float4*)(g_qkv[z] + (size_t)row*DIM);
        #pragma unroll
        for (int j=0;j<4;j++) o[lane + 32*j] = make_float4(ww*v[j].x, ww*v[j].y, ww*v[j].z, ww*v[j].w);
        return;
    }
    float s = 0.f, q = 0.f;
    #pragma unroll
    for (int j=0;j<4;j++){
        s += v[j].x+v[j].y+v[j].z+v[j].w;
        q += v[j].x*v[j].x+v[j].y*v[j].y+v[j].z*v[j].z+v[j].w*v[j].w;
    }
    #pragma unroll
    for (int o2=16;o2>0;o2>>=1){
        s += __shfl_xor_sync(0xFFFFFFFFu, s, o2);
        q += __shfl_xor_sync(0xFFFFFFFFu, q, o2);
    }
    float mean = s*(1.0f/DIM);
    float rstd = rsqrtf(q*(1.0f/DIM) - mean*mean + 1e-6f);
    int e = g_routes[c].edge[z];
    const float4* gg = (const float4*)(eg    + (size_t)e*DIM);
    const float4* bb = (const float4*)(ebeta + (size_t)e*DIM);
    float4* o = (float4*)(g_eln[z] + (size_t)row*DIM);
    #pragma unroll
    for (int j=0;j<4;j++){
        float4 g4 = gg[lane + 32*j], b4 = bb[lane + 32*j];
        float4 r;
        r.x=(v[j].x-mean)*rstd*g4.x+b4.x; r.y=(v[j].y-mean)*rstd*g4.y+b4.y;
        r.z=(v[j].z-mean)*rstd*g4.z+b4.z; r.w=(v[j].w-mean)*rstd*g4.w+b4.w;
        o[lane + 32*j] = r;
    }
}

// ---------------- edge GEMM (BK=32) ----------------
__global__ void __launch_bounds__(256) k_edge_gemm(int c, const float* __restrict__ eW, const float* __restrict__ eb){
    int z = blockIdx.z;
    if (!g_routes[c].has[z]) return;
    int op = g_routes[c].op[z];
    if (op == 4) return;
    int e = g_routes[c].edge[z];
    const float* A = (op <= 2) ? g_eln[z] : g_srcp[g_routes[c].src[z]];
    const float* W = eW + (size_t)e*DIM*DIM;
    int row0 = blockIdx.y*BM, col0 = blockIdx.x*64;
    float acc[8][4] = {};
    gemm_w32(A, W, row0, col0, acc);
    float w = g_routes[c].w[z];
    const float* bias = eb + (size_t)e*DIM;
    EPI_BEGIN
        v0 += bias[cc]; v1 += bias[cc+1];
        if (op==0){ v0=fmaxf(v0,0.f); v1=fmaxf(v1,0.f); }
        else if (op==1){ v0=geluf(v0); v1=geluf(v1); }
        *(float2*)&g_qkv[z][(size_t)rr*DIM + cc] = make_float2(w*v0, w*v1);
    EPI_END
}

// ---------------- node LN (act 0; warp-per-row) ----------------
__global__ void k_node_ln(int c, const float* __restrict__ ng, const float* __restrict__ nbeta){
    if (g_routes[c].act != 0) return;
    int w = threadIdx.x >> 5, lane = threadIdx.x & 31;
    int row = blockIdx.x*8 + w;
    const float4* x = (const float4*)(g_qkv[0] + (size_t)row*DIM);
    float4 v[4];
    #pragma unroll
    for (int j=0;j<4;j++) v[j] = x[lane + 32*j];
    float s = 0.f, q = 0.f;
    #pragma unroll
    for (int j=0;j<4;j++){
        s += v[j].x+v[j].y+v[j].z+v[j].w;
        q += v[j].x*v[j].x+v[j].y*v[j].y+v[j].z*v[j].z+v[j].w*v[j].w;
    }
    #pragma unroll
    for (int o2=16;o2>0;o2>>=1){
        s += __shfl_xor_sync(0xFFFFFFFFu, s, o2);
        q += __shfl_xor_sync(0xFFFFFFFFu, q, o2);
    }
    float mean = s*(1.0f/DIM);
    float rstd = rsqrtf(q*(1.0f/DIM) - mean*mean + 1e-6f);
    const float4* gg = (const float4*)(ng    + (size_t)c*DIM);
    const float4* bb = (const float4*)(nbeta + (size_t)c*DIM);
    float4* o = (float4*)(g_ln + (size_t)row*DIM);
    #pragma unroll
    for (int j=0;j<4;j++){
        float4 g4 = gg[lane + 32*j], b4 = bb[lane + 32*j];
        float4 r;
        r.x=(v[j].x-mean)*rstd*g4.x+b4.x; r.y=(v[j].y-mean)*rstd*g4.y+b4.y;
        r.z=(v[j].z-mean)*rstd*g4.z+b4.z; r.w=(v[j].w-mean)*rstd*g4.w+b4.w;
        o[lane + 32*j] = r;
    }
}

// ---------------- node GEMMs W0/W1/W2 (BK=32) ----------------
__global__ void __launch_bounds__(256) k_node_gemm123(int c, const float* __restrict__ nW, const float* __restrict__ nb){
    int act = g_routes[c].act;
    int z = blockIdx.z;
    const float* A; bool need, bias; int actf = 0;
    if (z == 0){
        need = (act==0||act==1||act==3);
        A = (act==0) ? g_ln : g_qkv[0];
        bias = (act!=3); actf = (act==1)?1:0;
    } else if (z == 1){
        need = (act==0||act==1||act==3||act==5);
        A = g_qkv[1];
        bias = (act!=3); actf = (act==5)?1:0;
    } else {
        need = (act==0||act==3);
        A = g_qkv[2];
        bias = (act==0);
    }
    if (!need) return;
    const float* W = nW + ((size_t)c*4 + z)*DIM*DIM;
    int row0 = blockIdx.y*BM, col0 = blockIdx.x*64;
    float acc[8][4] = {};
    gemm_w32(A, W, row0, col0, acc);
    const float* bp = nb + ((size_t)c*4 + z)*DIM;
    EPI_BEGIN
        if (bias){ v0 += bp[cc]; v1 += bp[cc+1]; }
        if (actf){ v0 = geluf(v0); v1 = geluf(v1); }
        *(float2*)&g_t[z][(size_t)rr*DIM + cc] = make_float2(v0, v1);
    EPI_END
}

// ---------------- elementwise mid (512 blocks) ----------------
__global__ void k_node_mid(int c){
    int act = g_routes[c].act;
    if (act != 1 && act != 3) return;
    #pragma unroll
    for (int j=0;j<4;j++){
        size_t i = (size_t)blockIdx.x*1024 + j*256 + threadIdx.x;
        float4 a = ((const float4*)g_t[0])[i];
        float4 b = ((const float4*)g_t[1])[i];
        float4 o;
        if (act == 1){
            o = make_float4(a.x*b.x, a.y*b.y, a.z*b.z, a.w*b.w);
        } else {
            float4 d = ((const float4*)g_t[2])[i];
            o = make_float4(fmaxf(a.x+b.x+d.x,0.f), fmaxf(a.y+b.y+d.y,0.f),
                            fmaxf(a.z+b.z+d.z,0.f), fmaxf(a.w+b.w+d.w,0.f));
        }
        ((float4*)g_t[3])[i] = o;
    }
}

// ---------------- attention ----------------
__global__ void __launch_bounds__(256) k_attn_scores(int c){
    if (g_routes[c].act != 0) return;
    int bz = blockIdx.z, b = bz >> 3, h = bz & 7;
    const float* A  = g_t[0] + (size_t)b*SLEN_*DIM + h*DH;
    const float* Bp = g_t[1] + (size_t)b*SLEN_*DIM + h*DH;
    int row0 = blockIdx.y*BM, col0 = blockIdx.x*64;
    float acc[8][4] = {};
    gemm_tc<true>(A, DIM, Bp, DIM, DH, row0, col0, acc);
    float* S = g_scores + (size_t)bz*SLEN_*SLEN_;
    EPI_BEGIN
        *(float2*)&S[(size_t)rr*SLEN_ + cc] = make_float2(v0*0.125f, v1*0.125f);
    EPI_END
}

__global__ void k_attn_softmax(int c){
    if (g_routes[c].act != 0) return;
    int bz = blockIdx.y;
    int w = threadIdx.x >> 5, lane = threadIdx.x & 31;
    #pragma unroll 1
    for (int rr = w; rr < 32; rr += 8){
        int row = blockIdx.x*32 + rr;
        float4* p = (float4*)(g_scores + ((size_t)bz*SLEN_ + row)*SLEN_);
        float4 v[8];
        float m = -1e30f;
        #pragma unroll
        for (int j=0;j<8;j++){
            v[j] = p[lane + 32*j];
            m = fmaxf(m, fmaxf(fmaxf(v[j].x,v[j].y), fmaxf(v[j].z,v[j].w)));
        }
        #pragma unroll
        for (int o=16;o>0;o>>=1) m = fmaxf(m, __shfl_xor_sync(0xFFFFFFFFu, m, o));
        float s = 0.f;
        #pragma unroll
        for (int j=0;j<8;j++){
            v[j].x=expf(v[j].x-m); v[j].y=expf(v[j].y-m);
            v[j].z=expf(v[j].z-m); v[j].w=expf(v[j].w-m);
            s += v[j].x+v[j].y+v[j].z+v[j].w;
        }
        #pragma unroll
        for (int o=16;o>0;o>>=1) s += __shfl_xor_sync(0xFFFFFFFFu, s, o);
        float inv = 1.0f/s;
        #pragma unroll
        for (int j=0;j<8;j++){
            v[j].x*=inv; v[j].y*=inv; v[j].z*=inv; v[j].w*=inv;
            p[lane + 32*j] = v[j];
        }
    }
}

__global__ void __launch_bounds__(256) k_attn_av(int c){
    if (g_routes[c].act != 0) return;
    int bz = blockIdx.z, b = bz >> 3, h = bz & 7;
    const float* A  = g_scores + (size_t)bz*SLEN_*SLEN_;
    const float* Bp = g_t[2] + (size_t)b*SLEN_*DIM + h*DH;
    int row0 = blockIdx.y*BM, col0 = 0;
    float acc[8][4] = {};
    gemm_tc<false>(A, SLEN_, Bp, DIM, SLEN_, row0, col0, acc);
    EPI_BEGIN
        *(float2*)&g_t[3][(size_t)(b*SLEN_ + rr)*DIM + h*DH + cc] = make_float2(v0, v1);
    EPI_END
}

// ---------------- node GEMM W3 (BK=32, fused residual + aw) ----------------
__global__ void __launch_bounds__(256) k_node_gemm4(int c, const float* __restrict__ nW, const float* __restrict__ nb){
    int act = g_routes[c].act;
    if (!(act==0||act==1||act==3)) return;
    const float* W = nW + ((size_t)c*4 + 3)*DIM*DIM;
    int row0 = blockIdx.y*BM, col0 = blockIdx.x*64;
    float acc[8][4] = {};
    gemm_w32(g_t[3], W, row0, col0, acc);
    const float* bp = nb + ((size_t)c*4 + 3)*DIM;
    float aw = g_routes[c].aw;
    float* outp = g_outs[2+c];
    EPI_BEGIN
        float2 q = *(const float2*)&g_qkv[0][(size_t)rr*DIM + cc];
        *(float2*)&outp[(size_t)rr*DIM + cc] =
            make_float2(aw*(q.x + v0 + bp[cc]), aw*(q.y + v1 + bp[cc+1]));
    EPI_END
}

// ---------------- node finalize (acts 2,4,5,6,7; warp-per-row) ----------------
__global__ void k_node_final(int c, const float* __restrict__ ng, const float* __restrict__ nbeta){
    int act = g_routes[c].act;
    if (act==0 || act==1 || act==3) return;
    float aw = g_routes[c].aw;
    int w = threadIdx.x >> 5, lane = threadIdx.x & 31;
    int row = blockIdx.x*8 + w;
    size_t off = (size_t)row*DIM;
    const float4* qp = (const float4*)(g_qkv[0] + off);
    float4 q[4];
    #pragma unroll
    for (int j=0;j<4;j++) q[j] = qp[lane + 32*j];
    float4 o[4];
    bool needln = false;
    float4 x[4];
    if (act==5){
        const float4* tp = (const float4*)(g_t[1] + off);
        #pragma unroll
        for (int j=0;j<4;j++){
            float4 t1 = tp[lane + 32*j];
            o[j] = make_float4(q[j].x+t1.x, q[j].y+t1.y, q[j].z+t1.z, q[j].w+t1.w);
        }
    } else if (act==2){
        const float4* kp = (const float4*)(g_qkv[1] + off);
        const float4* vp = (const float4*)(g_qkv[2] + off);
        #pragma unroll
        for (int j=0;j<4;j++){
            float4 k = kp[lane + 32*j], v = vp[lane + 32*j];
            x[j] = make_float4(q[j].x+k.x+v.x, q[j].y+k.y+v.y, q[j].z+k.z+v.z, q[j].w+k.w+v.w);
        }
        needln = true;
    } else if (act==4){
        const float4* kp = (const float4*)(g_qkv[1] + off);
        const float4* vp = (const float4*)(g_qkv[2] + off);
        #pragma unroll
        for (int j=0;j<4;j++){
            float4 k = kp[lane + 32*j], v = vp[lane + 32*j];
            o[j] = make_float4(q[j].x*sigm(k.x)+v.x, q[j].y*sigm(k.y)+v.y,
                               q[j].z*sigm(k.z)+v.z, q[j].w*sigm(k.w)+v.w);
        }
    } else if (act==6){
        const float4* kp = (const float4*)(g_qkv[1] + off);
        #pragma unroll
        for (int j=0;j<4;j++){
            float4 k = kp[lane + 32*j];
            o[j] = make_float4(q[j].x+k.x, q[j].y+k.y, q[j].z+k.z, q[j].w+k.w);
        }
    } else {
        #pragma unroll
        for (int j=0;j<4;j++) x[j] = q[j];
        needln = true;
    }
    if (needln){
        float s = 0.f, qq = 0.f;
        #pragma unroll
        for (int j=0;j<4;j++){
            s += x[j].x+x[j].y+x[j].z+x[j].w;
            qq += x[j].x*x[j].x+x[j].y*x[j].y+x[j].z*x[j].z+x[j].w*x[j].w;
        }
        #pragma unroll
        for (int o2=16;o2>0;o2>>=1){
            s += __shfl_xor_sync(0xFFFFFFFFu, s, o2);
            qq += __shfl_xor_sync(0xFFFFFFFFu, qq, o2);
        }
        float mean = s*(1.0f/DIM);
        float rstd = rsqrtf(qq*(1.0f/DIM) - mean*mean + 1e-6f);
        const float4* gg = (const float4*)(ng    + (size_t)c*DIM);
        const float4* bb = (const float4*)(nbeta + (size_t)c*DIM);
        #pragma unroll
        for (int j=0;j<4;j++){
            float4 g4 = gg[lane + 32*j], b4 = bb[lane + 32*j];
            o[j].x=(x[j].x-mean)*rstd*g4.x+b4.x; o[j].y=(x[j].y-mean)*rstd*g4.y+b4.y;
            o[j].z=(x[j].z-mean)*rstd*g4.z+b4.z; o[j].w=(x[j].w-mean)*rstd*g4.w+b4.w;
        }
    }
    float4* op = (float4*)(g_outs[2+c] + off);
    #pragma unroll
    for (int j=0;j<4;j++){
        o[j].x*=aw; o[j].y*=aw; o[j].z*=aw; o[j].w*=aw;
        op[lane + 32*j] = o[j];
    }
}

// ---------------- final sum + LN (warp-per-row) ----------------
__global__ void k_final(const float* __restrict__ og, const float* __restrict__ ob, float* __restrict__ out){
    int w = threadIdx.x >> 5, lane = threadIdx.x & 31;
    int row = blockIdx.x*8 + w;
    size_t off = (size_t)row*DIM;
    float4 s4[4];
    #pragma unroll
    for (int j=0;j<4;j++) s4[j] = make_float4(0.f,0.f,0.f,0.f);
    #pragma unroll
    for (int n=0;n<8;n++){
        if (g_rem[n]){
            const float4* vp = (const float4*)(g_outs[2+n] + off);
            #pragma unroll
            for (int j=0;j<4;j++){
                float4 v = vp[lane + 32*j];
                s4[j].x+=v.x; s4[j].y+=v.y; s4[j].z+=v.z; s4[j].w+=v.w;
            }
        }
    }
    float s = 0.f, q = 0.f;
    #pragma unroll
    for (int j=0;j<4;j++){
        s += s4[j].x+s4[j].y+s4[j].z+s4[j].w;
        q += s4[j].x*s4[j].x+s4[j].y*s4[j].y+s4[j].z*s4[j].z+s4[j].w*s4[j].w;
    }
    #pragma unroll
    for (int o2=16;o2>0;o2>>=1){
        s += __shfl_xor_sync(0xFFFFFFFFu, s, o2);
        q += __shfl_xor_sync(0xFFFFFFFFu, q, o2);
    }
    float mean = s*(1.0f/DIM);
    float rstd = rsqrtf(q*(1.0f/DIM) - mean*mean + 1e-6f);
    const float4* gg = (const float4*)og;
    const float4* bb = (const float4*)ob;
    float4* op = (float4*)(out + off);
    #pragma unroll
    for (int j=0;j<4;j++){
        float4 g4 = gg[lane + 32*j], b4 = bb[lane + 32*j];
        float4 o;
        o.x=(s4[j].x-mean)*rstd*g4.x+b4.x; o.y=(s4[j].y-mean)*rstd*g4.y+b4.y;
        o.z=(s4[j].z-mean)*rstd*g4.z+b4.z; o.w=(s4[j].w-mean)*rstd*g4.w+b4.w;
        op[lane + 32*j] = o;
    }
}

// ---------------- launch ----------------
extern "C" void kernel_launch(void* const* d_in, const int* in_sizes, int n_in,
                              void* d_out, int out_size)
{
    const float* inpute    = (const float*)d_in[0];
    const float* inputo    = (const float*)d_in[1];
    const float* node_p    = (const float*)d_in[2];
    const float* edge_p    = (const float*)d_in[3];
    const float* edge_W    = (const float*)d_in[4];
    const float* edge_b    = (const float*)d_in[5];
    const float* edge_g    = (const float*)d_in[6];
    const float* edge_beta = (const float*)d_in[7];
    const float* node_W    = (const float*)d_in[8];
    const float* node_b    = (const float*)d_in[9];
    const float* node_g    = (const float*)d_in[10];
    const float* node_beta = (const float*)d_in[11];
    const float* out_g     = (const float*)d_in[12];
    const float* out_beta  = (const float*)d_in[13];
    float* out = (float*)d_out;

    cudaFuncSetAttribute(k_edge_gemm,    cudaFuncAttributeMaxDynamicSharedMemorySize, W_SMEM);
    cudaFuncSetAttribute(k_node_gemm123, cudaFuncAttributeMaxDynamicSharedMemorySize, W_SMEM);
    cudaFuncSetAttribute(k_node_gemm4,   cudaFuncAttributeMaxDynamicSharedMemorySize, W_SMEM);

    k_route<<<1, 32>>>(node_p, edge_p, inpute, inputo);

    for (int c = 0; c < 8; c++){
        k_edge_prep<<<dim3(NROW/8,1,3), 256>>>(c, edge_g, edge_beta);
        k_edge_gemm<<<dim3(DIM/64, NROW/BM, 3), 256, W_SMEM>>>(c, edge_W, edge_b);
        k_node_ln<<<NROW/8, 256>>>(c, node_g, node_beta);
        k_node_gemm123<<<dim3(DIM/64, NROW/BM, 3), 256, W_SMEM>>>(c, node_W, node_b);
        k_node_mid<<<NMELEM/4/1024, 256>>>(c);
        k_attn_scores<<<dim3(SLEN_/64, SLEN_/BM, 32), 256>>>(c);
        k_attn_softmax<<<dim3(SLEN_/32, 32), 256>>>(c);
        k_attn_av<<<dim3(1, SLEN_/BM, 32), 256>>>(c);
        k_node_gemm4<<<dim3(DIM/64, NROW/BM), 256, W_SMEM>>>(c, node_W, node_b);
        k_node_final<<<NROW/8, 256>>>(c, node_g, node_beta);
    }
    k_final<<<NROW/8, 256>>>(out_g, out_beta, out);
}